// round 2
// baseline (speedup 1.0000x reference)
#include <cuda_runtime.h>
#include <cuda_bf16.h>
#include <cstdint>

// Problem constants
#define NROWS   100352        // 2048 windows * 49 tokens
#define DIM     512
#define QKVDIM  1536
#define NWIN    2048
#define NTOK    49
#define NHEAD   16
#define DH      32
#define NMEM    4
#define NCTX    53            // NMEM + NTOK

// ---------------------------------------------------------------------------
// Scratch (device globals: no allocation allowed anywhere)
// ---------------------------------------------------------------------------
__device__ float g_mu[NROWS];
__device__ float g_rstd[NROWS];
__device__ float g_qkv[(size_t)NROWS * QKVDIM];   // 616 MB
__device__ float g_att[(size_t)NROWS * DIM];      // 205 MB

// ---------------------------------------------------------------------------
// f32x2 helpers (sm_100+ packed fp32 FMA; FFMA-3reg is half rate on sm_103a)
// ---------------------------------------------------------------------------
__device__ __forceinline__ void ffma2(unsigned long long& acc,
                                      unsigned long long a,
                                      unsigned long long b) {
    asm("fma.rn.f32x2 %0, %1, %2, %0;" : "+l"(acc) : "l"(a), "l"(b));
}
__device__ __forceinline__ unsigned long long pack2(float a) {
    unsigned long long d;
    asm("mov.b64 %0, {%1, %1};" : "=l"(d) : "f"(a));
    return d;
}
union F2U { unsigned long long u; float2 f; };

// ---------------------------------------------------------------------------
// Kernel 1: LayerNorm statistics (mean, rstd) per row of 512
// ---------------------------------------------------------------------------
__global__ void __launch_bounds__(256) ln_stats_kernel(const float* __restrict__ x) {
    int row  = blockIdx.x * 8 + (threadIdx.x >> 5);
    int lane = threadIdx.x & 31;
    const float4* xp = reinterpret_cast<const float4*>(x + (size_t)row * DIM);
    float s = 0.f, sq = 0.f;
#pragma unroll
    for (int i = 0; i < 4; i++) {
        float4 v = xp[lane + i * 32];
        s  += v.x + v.y + v.z + v.w;
        sq += v.x * v.x + v.y * v.y + v.z * v.z + v.w * v.w;
    }
#pragma unroll
    for (int o = 16; o; o >>= 1) {
        s  += __shfl_xor_sync(0xffffffffu, s,  o);
        sq += __shfl_xor_sync(0xffffffffu, sq, o);
    }
    if (lane == 0) {
        float m   = s * (1.f / DIM);
        float var = sq * (1.f / DIM) - m * m;
        g_mu[row]   = m;
        g_rstd[row] = rsqrtf(var + 1e-5f);
    }
}

// ---------------------------------------------------------------------------
// GEMM: C[M,N] = A[M,K] @ B[K,N], 128x128x16 tiles, 8x8 per thread, f32x2 acc.
// MODE 0: A = x input with LayerNorm folded into load, C = g_qkv
// MODE 1: A = g_att, C = output param
// ---------------------------------------------------------------------------
#define BM 128
#define BN 128
#define BK 16

template <int MODE>
__global__ void __launch_bounds__(256, 2) gemm_kernel(
    const float* __restrict__ Ain, const float* __restrict__ Bmat,
    float* __restrict__ Cout, int M, int N, int K,
    const float* __restrict__ gamma, const float* __restrict__ beta)
{
    __shared__ float As[BK][BM + 4];
    __shared__ float Bs[BK][BN];

    const float* __restrict__ A = (MODE == 0) ? Ain : g_att;
    float* __restrict__ C       = (MODE == 0) ? g_qkv : Cout;

    const int tid = threadIdx.x;
    const int bm  = blockIdx.y * BM;
    const int bn  = blockIdx.x * BN;
    const int tx  = tid & 15;
    const int ty  = tid >> 4;
    const int m0t = ty * 8;
    const int n0t = tx * 8;

    unsigned long long acc[8][4];
#pragma unroll
    for (int i = 0; i < 8; i++)
#pragma unroll
        for (int j = 0; j < 4; j++) acc[i][j] = 0ull;

    for (int k0 = 0; k0 < K; k0 += BK) {
        // ---- load A tile (128 rows x 16 cols), transpose into As[k][m]
#pragma unroll
        for (int u = 0; u < 2; u++) {
            int idx = tid + u * 256;          // float4 index, 0..511
            int r   = idx >> 2;               // row within tile
            int cq  = (idx & 3) << 2;         // k offset (0,4,8,12)
            float4 av = *reinterpret_cast<const float4*>(
                A + (size_t)(bm + r) * K + k0 + cq);
            float x0 = av.x, x1 = av.y, x2 = av.z, x3 = av.w;
            if (MODE == 0) {
                float mu_ = g_mu[bm + r];
                float rs_ = g_rstd[bm + r];
                x0 = (x0 - mu_) * rs_ * gamma[k0 + cq + 0] + beta[k0 + cq + 0];
                x1 = (x1 - mu_) * rs_ * gamma[k0 + cq + 1] + beta[k0 + cq + 1];
                x2 = (x2 - mu_) * rs_ * gamma[k0 + cq + 2] + beta[k0 + cq + 2];
                x3 = (x3 - mu_) * rs_ * gamma[k0 + cq + 3] + beta[k0 + cq + 3];
            }
            As[cq + 0][r] = x0;
            As[cq + 1][r] = x1;
            As[cq + 2][r] = x2;
            As[cq + 3][r] = x3;
        }
        // ---- load B tile (16 rows x 128 cols)
#pragma unroll
        for (int u = 0; u < 2; u++) {
            int idx = tid + u * 256;
            int kr  = idx >> 5;
            int cf  = (idx & 31) << 2;
            *reinterpret_cast<float4*>(&Bs[kr][cf]) =
                *reinterpret_cast<const float4*>(Bmat + (size_t)(k0 + kr) * N + bn + cf);
        }
        __syncthreads();

#pragma unroll
        for (int k = 0; k < BK; k++) {
            float4 a0 = *reinterpret_cast<const float4*>(&As[k][m0t]);
            float4 a1 = *reinterpret_cast<const float4*>(&As[k][m0t + 4]);
            unsigned long long b0 = *reinterpret_cast<const unsigned long long*>(&Bs[k][n0t + 0]);
            unsigned long long b1 = *reinterpret_cast<const unsigned long long*>(&Bs[k][n0t + 2]);
            unsigned long long b2 = *reinterpret_cast<const unsigned long long*>(&Bs[k][n0t + 4]);
            unsigned long long b3 = *reinterpret_cast<const unsigned long long*>(&Bs[k][n0t + 6]);
            float am[8] = {a0.x, a0.y, a0.z, a0.w, a1.x, a1.y, a1.z, a1.w};
#pragma unroll
            for (int mi = 0; mi < 8; mi++) {
                unsigned long long aa = pack2(am[mi]);
                ffma2(acc[mi][0], aa, b0);
                ffma2(acc[mi][1], aa, b1);
                ffma2(acc[mi][2], aa, b2);
                ffma2(acc[mi][3], aa, b3);
            }
        }
        __syncthreads();
    }

    // ---- epilogue
#pragma unroll
    for (int mi = 0; mi < 8; mi++) {
        float o[8];
#pragma unroll
        for (int nj = 0; nj < 4; nj++) {
            F2U u; u.u = acc[mi][nj];
            o[nj * 2 + 0] = u.f.x;
            o[nj * 2 + 1] = u.f.y;
        }
        float4* cp = reinterpret_cast<float4*>(
            C + (size_t)(bm + m0t + mi) * N + bn + n0t);
        cp[0] = make_float4(o[0], o[1], o[2], o[3]);
        cp[1] = make_float4(o[4], o[5], o[6], o[7]);
    }
}

// ---------------------------------------------------------------------------
// Kernel 3: windowed attention, one block per (window, head)
// q,k,v in smem; rel bias + mem-kv prepend; softmax; out -> g_att merged heads
// ---------------------------------------------------------------------------
__global__ void __launch_bounds__(128) attn_kernel(
    const float* __restrict__ mem_kv,
    const float* __restrict__ rel_bias,
    const int*   __restrict__ rel_idx)
{
    const int w = blockIdx.x;
    const int h = blockIdx.y;
    const int tid = threadIdx.x;

    __shared__ float q_s[NTOK][36];
    __shared__ float k_s[NCTX][36];
    __shared__ float v_s[NCTX][36];
    __shared__ float sim[NTOK][NCTX];

    const size_t base = (size_t)w * NTOK * QKVDIM;
    const int hcol = h * DH;

    for (int idx = tid; idx < NTOK * DH; idx += 128) {
        int i = idx >> 5, d = idx & 31;
        q_s[i][d] = g_qkv[base + (size_t)i * QKVDIM + hcol + d];
    }
    for (int idx = tid; idx < NCTX * DH; idx += 128) {
        int j = idx >> 5, d = idx & 31;
        if (j < NMEM) {
            k_s[j][d] = mem_kv[(h * NMEM + j) * DH + d];
            v_s[j][d] = mem_kv[NHEAD * NMEM * DH + (h * NMEM + j) * DH + d];
        } else {
            size_t rb = base + (size_t)(j - NMEM) * QKVDIM + hcol + d;
            k_s[j][d] = g_qkv[rb + DIM];
            v_s[j][d] = g_qkv[rb + 2 * DIM];
        }
    }
    __syncthreads();

    const float scale = 0.17677669529663687f;  // 1/sqrt(32)
    for (int idx = tid; idx < NTOK * NCTX; idx += 128) {
        int i = idx / NCTX;
        int j = idx - i * NCTX;
        const float4* qp = reinterpret_cast<const float4*>(q_s[i]);
        const float4* kp = reinterpret_cast<const float4*>(k_s[j]);
        float acc = 0.f;
#pragma unroll
        for (int c = 0; c < 8; c++) {
            float4 a = qp[c], b = kp[c];
            acc += a.x * b.x + a.y * b.y + a.z * b.z + a.w * b.w;
        }
        float bias = 0.f;
        if (j >= NMEM) bias = rel_bias[rel_idx[i * NTOK + (j - NMEM)] * NHEAD + h];
        sim[i][j] = acc * scale + bias;
    }
    __syncthreads();

    // softmax over 53, one warp per row (4 warps, strided rows)
    const int wp = tid >> 5, lane = tid & 31;
    for (int i = wp; i < NTOK; i += 4) {
        float s0 = sim[i][lane];
        float s1 = (lane < NCTX - 32) ? sim[i][lane + 32] : -1e30f;
        float m = fmaxf(s0, s1);
#pragma unroll
        for (int o = 16; o; o >>= 1) m = fmaxf(m, __shfl_xor_sync(0xffffffffu, m, o));
        float e0 = __expf(s0 - m);
        float e1 = (lane < NCTX - 32) ? __expf(s1 - m) : 0.f;
        float s = e0 + e1;
#pragma unroll
        for (int o = 16; o; o >>= 1) s += __shfl_xor_sync(0xffffffffu, s, o);
        float inv = 1.f / s;
        sim[i][lane] = e0 * inv;
        if (lane < NCTX - 32) sim[i][lane + 32] = e1 * inv;
    }
    __syncthreads();

    // out = P @ V, write merged-head layout (row, h*32+d)
    for (int idx = tid; idx < NTOK * DH; idx += 128) {
        int i = idx >> 5, d = idx & 31;
        float acc = 0.f;
#pragma unroll
        for (int j = 0; j < NCTX; j++) acc += sim[i][j] * v_s[j][d];
        g_att[((size_t)w * NTOK + i) * DIM + hcol + d] = acc;
    }
}

// ---------------------------------------------------------------------------
// Launch
// ---------------------------------------------------------------------------
extern "C" void kernel_launch(void* const* d_in, const int* in_sizes, int n_in,
                              void* d_out, int out_size) {
    const float* x        = (const float*)d_in[0];
    const float* ln_gamma = (const float*)d_in[1];
    const float* ln_beta  = (const float*)d_in[2];
    const float* w_qkv    = (const float*)d_in[3];
    const float* mem_kv   = (const float*)d_in[4];
    const float* w_out    = (const float*)d_in[5];
    const float* rel_bias = (const float*)d_in[6];
    const int*   rel_idx  = (const int*)d_in[7];
    float* out = (float*)d_out;

    // 1) LN stats
    ln_stats_kernel<<<NROWS / 8, 256>>>(x);

    // 2) QKV GEMM with LN folded into A load: g_qkv = LN(x) @ w_qkv
    gemm_kernel<0><<<dim3(QKVDIM / BN, NROWS / BM), 256>>>(
        x, w_qkv, nullptr, NROWS, QKVDIM, DIM, ln_gamma, ln_beta);

    // 3) windowed attention per (window, head) -> g_att
    attn_kernel<<<dim3(NWIN, NHEAD), 128>>>(mem_kv, rel_bias, rel_idx);

    // 4) output projection: out = g_att @ w_out
    gemm_kernel<1><<<dim3(DIM / BN, NROWS / BM), 256>>>(
        nullptr, w_out, out, NROWS, DIM, DIM, nullptr, nullptr);
}

// round 4
// speedup vs baseline: 1.4443x; 1.4443x over previous
#include <cuda_runtime.h>
#include <cuda_bf16.h>
#include <cstdint>

// Problem constants
#define NROWS   100352        // 2048 windows * 49 tokens
#define DIM     512
#define QKVDIM  1536
#define NWIN    2048
#define NTOK    49
#define NHEAD   16
#define DH      32
#define NMEM    4
#define NCTX    53            // NMEM + NTOK
#define GK      512           // GEMM K (both GEMMs)

// ---------------------------------------------------------------------------
// Scratch (device globals: no allocation allowed anywhere)
// ---------------------------------------------------------------------------
__device__ float g_mu[NROWS];
__device__ float g_rstd[NROWS];
__device__ float g_qkv[(size_t)NROWS * QKVDIM];    // 616 MB
__device__ float g_att[(size_t)NROWS * DIM];       // 205 MB
__device__ float g_wqkv_t[(size_t)QKVDIM * DIM];   // w_qkv transposed [N][K]
__device__ float g_wout_t[(size_t)DIM * DIM];      // w_out transposed  [N][K]

// ---------------------------------------------------------------------------
// PTX helpers (baseline PTX only -- the harness builds for compute_103,
// which rejects tcgen05/sm_103a-specific instructions)
// ---------------------------------------------------------------------------
__device__ __forceinline__ uint32_t smem_u32(const void* p) {
    uint32_t a;
    asm("{ .reg .u64 t; cvta.to.shared.u64 t, %1; cvt.u32.u64 %0, t; }" : "=r"(a) : "l"(p));
    return a;
}

__device__ __forceinline__ void ldmx4(uint32_t* r, uint32_t addr) {
    asm volatile("ldmatrix.sync.aligned.m8n8.x4.shared.b16 {%0,%1,%2,%3}, [%4];"
        : "=r"(r[0]), "=r"(r[1]), "=r"(r[2]), "=r"(r[3]) : "r"(addr));
}

__device__ __forceinline__ void mma_bf16(float* c, const uint32_t* a, const uint32_t* b) {
    asm volatile(
        "mma.sync.aligned.m16n8k16.row.col.f32.bf16.bf16.f32 "
        "{%0,%1,%2,%3}, {%4,%5,%6,%7}, {%8,%9}, {%0,%1,%2,%3};"
        : "+f"(c[0]), "+f"(c[1]), "+f"(c[2]), "+f"(c[3])
        : "r"(a[0]), "r"(a[1]), "r"(a[2]), "r"(a[3]), "r"(b[0]), "r"(b[1]));
}

// ---------------------------------------------------------------------------
// Kernel 1: LayerNorm statistics (mean, rstd) per row of 512
// ---------------------------------------------------------------------------
__global__ void __launch_bounds__(256) ln_stats_kernel(const float* __restrict__ x) {
    int row  = blockIdx.x * 8 + (threadIdx.x >> 5);
    int lane = threadIdx.x & 31;
    const float4* xp = reinterpret_cast<const float4*>(x + (size_t)row * DIM);
    float s = 0.f, sq = 0.f;
#pragma unroll
    for (int i = 0; i < 4; i++) {
        float4 v = xp[lane + i * 32];
        s  += v.x + v.y + v.z + v.w;
        sq += v.x * v.x + v.y * v.y + v.z * v.z + v.w * v.w;
    }
#pragma unroll
    for (int o = 16; o; o >>= 1) {
        s  += __shfl_xor_sync(0xffffffffu, s,  o);
        sq += __shfl_xor_sync(0xffffffffu, sq, o);
    }
    if (lane == 0) {
        float m   = s * (1.f / DIM);
        float var = sq * (1.f / DIM) - m * m;
        g_mu[row]   = m;
        g_rstd[row] = rsqrtf(var + 1e-5f);
    }
}

// ---------------------------------------------------------------------------
// Kernel 2: transpose weights [K,N] row-major -> [N,K] row-major
// ---------------------------------------------------------------------------
__global__ void __launch_bounds__(256) transpose_kernel(const float* __restrict__ src,
                                                        float* __restrict__ dst,
                                                        int K, int N) {
    __shared__ float t[32][33];
    int bx = blockIdx.x * 32;   // n base
    int by = blockIdx.y * 32;   // k base
    int tx = threadIdx.x & 31, ty = threadIdx.x >> 5;
#pragma unroll
    for (int u = 0; u < 4; u++)
        t[ty + u * 8][tx] = src[(size_t)(by + ty + u * 8) * N + bx + tx];
    __syncthreads();
#pragma unroll
    for (int u = 0; u < 4; u++)
        dst[(size_t)(bx + ty + u * 8) * K + by + tx] = t[tx][ty + u * 8];
}

// ---------------------------------------------------------------------------
// Tensor-core GEMM via mma.sync bf16 with 2-term split (hi+lo):
//   C = A @ B^T_t  with A fp32, precision ~1e-5 rel (lo*lo dropped).
// CTA tile 128x128, K-slab 32. 8 warps, warp tile 64x32.
// MODE 0: A = LN(x) folded at stage time, C = g_qkv (N=1536)
// MODE 1: A = g_att, C = out (N=512)
// ---------------------------------------------------------------------------
template <int MODE>
__global__ void __launch_bounds__(256) gemm_mma_kernel(
    const float* __restrict__ Ain, float* __restrict__ Cout,
    const float* __restrict__ gamma, const float* __restrict__ beta)
{
    // stride 40 bf16 (80 B) rows: conflict-free for ldmatrix 8-address groups
    __shared__ __nv_bfloat16 sA_hi[128][40];
    __shared__ __nv_bfloat16 sA_lo[128][40];
    __shared__ __nv_bfloat16 sB_hi[128][40];
    __shared__ __nv_bfloat16 sB_lo[128][40];

    const int N = (MODE == 0) ? QKVDIM : DIM;
    const float* __restrict__ A  = (MODE == 0) ? Ain : g_att;
    const float* __restrict__ Bt = (MODE == 0) ? g_wqkv_t : g_wout_t;
    float* __restrict__ C        = (MODE == 0) ? g_qkv : Cout;

    const int tid  = threadIdx.x;
    const int lane = tid & 31;
    const int wid  = tid >> 5;
    const int bm   = blockIdx.y * 128;
    const int bn   = blockIdx.x * 128;
    const int wm   = (wid & 1) * 64;     // warp m-offset within CTA tile
    const int wn   = (wid >> 1) * 32;    // warp n-offset

    float c[4][4][4];
#pragma unroll
    for (int i = 0; i < 4; i++)
#pragma unroll
        for (int j = 0; j < 4; j++)
#pragma unroll
            for (int l = 0; l < 4; l++) c[i][j][l] = 0.f;

    // staging registers for the next K-slab (A and B tiles: 128x32 fp32 each)
    float4 ra[4], rb[4];

    auto load_tiles = [&](int k0) {
#pragma unroll
        for (int u = 0; u < 4; u++) {
            int idx = tid + u * 256;          // float4 id 0..1023
            int r   = idx >> 3;               // tile row (8 float4 per 32-col row)
            int c4  = (idx & 7) << 2;         // k offset
            float4 av = *reinterpret_cast<const float4*>(A + (size_t)(bm + r) * GK + k0 + c4);
            if (MODE == 0) {
                float mu_ = g_mu[bm + r], rs_ = g_rstd[bm + r];
                float4 gm = *reinterpret_cast<const float4*>(gamma + k0 + c4);
                float4 bt = *reinterpret_cast<const float4*>(beta + k0 + c4);
                av.x = (av.x - mu_) * rs_ * gm.x + bt.x;
                av.y = (av.y - mu_) * rs_ * gm.y + bt.y;
                av.z = (av.z - mu_) * rs_ * gm.z + bt.z;
                av.w = (av.w - mu_) * rs_ * gm.w + bt.w;
            }
            ra[u] = av;
            rb[u] = *reinterpret_cast<const float4*>(Bt + (size_t)(bn + r) * GK + k0 + c4);
        }
    };

    auto split_store = [&](float4 v, __nv_bfloat16* hp, __nv_bfloat16* lp) {
        __nv_bfloat16 h0 = __float2bfloat16_rn(v.x);
        __nv_bfloat16 h1 = __float2bfloat16_rn(v.y);
        __nv_bfloat16 h2 = __float2bfloat16_rn(v.z);
        __nv_bfloat16 h3 = __float2bfloat16_rn(v.w);
        __nv_bfloat16 l0 = __float2bfloat16_rn(v.x - __bfloat162float(h0));
        __nv_bfloat16 l1 = __float2bfloat16_rn(v.y - __bfloat162float(h1));
        __nv_bfloat16 l2 = __float2bfloat16_rn(v.z - __bfloat162float(h2));
        __nv_bfloat16 l3 = __float2bfloat16_rn(v.w - __bfloat162float(h3));
        reinterpret_cast<__nv_bfloat162*>(hp)[0] = __nv_bfloat162(h0, h1);
        reinterpret_cast<__nv_bfloat162*>(hp)[1] = __nv_bfloat162(h2, h3);
        reinterpret_cast<__nv_bfloat162*>(lp)[0] = __nv_bfloat162(l0, l1);
        reinterpret_cast<__nv_bfloat162*>(lp)[1] = __nv_bfloat162(l2, l3);
    };

    auto store_tiles = [&]() {
#pragma unroll
        for (int u = 0; u < 4; u++) {
            int idx = tid + u * 256;
            int r   = idx >> 3;
            int c4  = (idx & 7) << 2;
            split_store(ra[u], &sA_hi[r][c4], &sA_lo[r][c4]);
            split_store(rb[u], &sB_hi[r][c4], &sB_lo[r][c4]);
        }
    };

    load_tiles(0);

    for (int it = 0; it < 16; ++it) {
        store_tiles();
        __syncthreads();
        if (it + 1 < 16) load_tiles((it + 1) * 32);   // prefetch next slab

        // A-fragment ldmatrix addressing: row = (lane&15), k-half = (lane>>4)*8
        const int arow = lane & 15;
        const int akof = (lane >> 4) << 3;
        // B-fragment addressing: n = (lane&7) + ((lane>>4)<<3), k = ((lane>>3)&1)*8
        const int brow = (lane & 7) + ((lane >> 4) << 3);
        const int bkof = ((lane >> 3) & 1) << 3;

#pragma unroll
        for (int h = 0; h < 2; h++) {                 // two k16 halves of the slab
            uint32_t ah[4][4], al[4][4], bh[4][2], bl[4][2];
#pragma unroll
            for (int mt = 0; mt < 4; mt++) {
                ldmx4(ah[mt], smem_u32(&sA_hi[wm + mt * 16 + arow][h * 16 + akof]));
                ldmx4(al[mt], smem_u32(&sA_lo[wm + mt * 16 + arow][h * 16 + akof]));
            }
#pragma unroll
            for (int p = 0; p < 2; p++) {
                uint32_t r4[4];
                ldmx4(r4, smem_u32(&sB_hi[wn + p * 16 + brow][h * 16 + bkof]));
                bh[2 * p][0] = r4[0]; bh[2 * p][1] = r4[1];
                bh[2 * p + 1][0] = r4[2]; bh[2 * p + 1][1] = r4[3];
                ldmx4(r4, smem_u32(&sB_lo[wn + p * 16 + brow][h * 16 + bkof]));
                bl[2 * p][0] = r4[0]; bl[2 * p][1] = r4[1];
                bl[2 * p + 1][0] = r4[2]; bl[2 * p + 1][1] = r4[3];
            }
#pragma unroll
            for (int mt = 0; mt < 4; mt++)
#pragma unroll
                for (int nt = 0; nt < 4; nt++) mma_bf16(c[mt][nt], ah[mt], bh[nt]);
#pragma unroll
            for (int mt = 0; mt < 4; mt++)
#pragma unroll
                for (int nt = 0; nt < 4; nt++) mma_bf16(c[mt][nt], ah[mt], bl[nt]);
#pragma unroll
            for (int mt = 0; mt < 4; mt++)
#pragma unroll
                for (int nt = 0; nt < 4; nt++) mma_bf16(c[mt][nt], al[mt], bh[nt]);
        }
        __syncthreads();
    }

    // epilogue: mma C-fragment layout -> gmem (float2 stores)
#pragma unroll
    for (int mt = 0; mt < 4; mt++) {
        int row0 = bm + wm + mt * 16 + (lane >> 2);
#pragma unroll
        for (int nt = 0; nt < 4; nt++) {
            int col = bn + wn + nt * 8 + (lane & 3) * 2;
            *reinterpret_cast<float2*>(C + (size_t)row0 * N + col)
                = make_float2(c[mt][nt][0], c[mt][nt][1]);
            *reinterpret_cast<float2*>(C + (size_t)(row0 + 8) * N + col)
                = make_float2(c[mt][nt][2], c[mt][nt][3]);
        }
    }
}

// ---------------------------------------------------------------------------
// Kernel: windowed attention, one block per (window, head)
// ---------------------------------------------------------------------------
__global__ void __launch_bounds__(128) attn_kernel(
    const float* __restrict__ mem_kv,
    const float* __restrict__ rel_bias,
    const int*   __restrict__ rel_idx)
{
    const int w = blockIdx.x;
    const int h = blockIdx.y;
    const int tid = threadIdx.x;

    __shared__ float q_s[NTOK][36];
    __shared__ float k_s[NCTX][36];
    __shared__ float v_s[NCTX][36];
    __shared__ float sim[NTOK][NCTX];

    const size_t base = (size_t)w * NTOK * QKVDIM;
    const int hcol = h * DH;

    for (int idx = tid; idx < NTOK * DH; idx += 128) {
        int i = idx >> 5, d = idx & 31;
        q_s[i][d] = g_qkv[base + (size_t)i * QKVDIM + hcol + d];
    }
    for (int idx = tid; idx < NCTX * DH; idx += 128) {
        int j = idx >> 5, d = idx & 31;
        if (j < NMEM) {
            k_s[j][d] = mem_kv[(h * NMEM + j) * DH + d];
            v_s[j][d] = mem_kv[NHEAD * NMEM * DH + (h * NMEM + j) * DH + d];
        } else {
            size_t rb = base + (size_t)(j - NMEM) * QKVDIM + hcol + d;
            k_s[j][d] = g_qkv[rb + DIM];
            v_s[j][d] = g_qkv[rb + 2 * DIM];
        }
    }
    __syncthreads();

    const float scale = 0.17677669529663687f;  // 1/sqrt(32)
    for (int idx = tid; idx < NTOK * NCTX; idx += 128) {
        int i = idx / NCTX;
        int j = idx - i * NCTX;
        const float4* qp = reinterpret_cast<const float4*>(q_s[i]);
        const float4* kp = reinterpret_cast<const float4*>(k_s[j]);
        float acc = 0.f;
#pragma unroll
        for (int c = 0; c < 8; c++) {
            float4 a = qp[c], b = kp[c];
            acc += a.x * b.x + a.y * b.y + a.z * b.z + a.w * b.w;
        }
        float bias = 0.f;
        if (j >= NMEM) bias = rel_bias[rel_idx[i * NTOK + (j - NMEM)] * NHEAD + h];
        sim[i][j] = acc * scale + bias;
    }
    __syncthreads();

    const int wp = tid >> 5, lane = tid & 31;
    for (int i = wp; i < NTOK; i += 4) {
        float s0 = sim[i][lane];
        float s1 = (lane < NCTX - 32) ? sim[i][lane + 32] : -1e30f;
        float m = fmaxf(s0, s1);
#pragma unroll
        for (int o = 16; o; o >>= 1) m = fmaxf(m, __shfl_xor_sync(0xffffffffu, m, o));
        float e0 = __expf(s0 - m);
        float e1 = (lane < NCTX - 32) ? __expf(s1 - m) : 0.f;
        float s = e0 + e1;
#pragma unroll
        for (int o = 16; o; o >>= 1) s += __shfl_xor_sync(0xffffffffu, s, o);
        float inv = 1.f / s;
        sim[i][lane] = e0 * inv;
        if (lane < NCTX - 32) sim[i][lane + 32] = e1 * inv;
    }
    __syncthreads();

    for (int idx = tid; idx < NTOK * DH; idx += 128) {
        int i = idx >> 5, d = idx & 31;
        float acc = 0.f;
#pragma unroll
        for (int j = 0; j < NCTX; j++) acc += sim[i][j] * v_s[j][d];
        g_att[((size_t)w * NTOK + i) * DIM + hcol + d] = acc;
    }
}

// ---------------------------------------------------------------------------
// Launch
// ---------------------------------------------------------------------------
extern "C" void kernel_launch(void* const* d_in, const int* in_sizes, int n_in,
                              void* d_out, int out_size) {
    const float* x        = (const float*)d_in[0];
    const float* ln_gamma = (const float*)d_in[1];
    const float* ln_beta  = (const float*)d_in[2];
    const float* w_qkv    = (const float*)d_in[3];
    const float* mem_kv   = (const float*)d_in[4];
    const float* w_out    = (const float*)d_in[5];
    const float* rel_bias = (const float*)d_in[6];
    const int*   rel_idx  = (const int*)d_in[7];
    float* out = (float*)d_out;

    // resolve device-global scratch addresses for the transpose targets
    float* wqkv_t_p; cudaGetSymbolAddress((void**)&wqkv_t_p, g_wqkv_t);
    float* wout_t_p; cudaGetSymbolAddress((void**)&wout_t_p, g_wout_t);

    // 1) LN stats
    ln_stats_kernel<<<NROWS / 8, 256>>>(x);

    // 2) weight transposes (tiny)
    transpose_kernel<<<dim3(QKVDIM / 32, DIM / 32), 256>>>(w_qkv, wqkv_t_p, DIM, QKVDIM);
    transpose_kernel<<<dim3(DIM / 32, DIM / 32), 256>>>(w_out, wout_t_p, DIM, DIM);

    // 3) QKV GEMM (tensor cores, LN folded): g_qkv = LN(x) @ w_qkv
    gemm_mma_kernel<0><<<dim3(QKVDIM / 128, NROWS / 128), 256>>>(
        x, nullptr, ln_gamma, ln_beta);

    // 4) windowed attention per (window, head) -> g_att
    attn_kernel<<<dim3(NWIN, NHEAD), 128>>>(mem_kv, rel_bias, rel_idx);

    // 5) output projection (tensor cores): out = g_att @ w_out
    gemm_mma_kernel<1><<<dim3(DIM / 128, NROWS / 128), 256>>>(
        nullptr, out, nullptr, nullptr);
}

// round 5
// speedup vs baseline: 1.8271x; 1.2651x over previous
#include <cuda_runtime.h>
#include <cuda_bf16.h>
#include <cstdint>

// Problem constants
#define NROWS   100352        // 2048 windows * 49 tokens
#define DIM     512
#define QKVDIM  1536
#define NWIN    2048
#define NTOK    49
#define NHEAD   16
#define DH      32
#define NMEM    4
#define NCTX    53            // NMEM + NTOK
#define GK      512           // GEMM K (both GEMMs)

// ---------------------------------------------------------------------------
// Scratch (device globals: no allocation allowed anywhere)
// ---------------------------------------------------------------------------
__device__ float g_qkv[(size_t)NROWS * QKVDIM];           // 616 MB fp32
__device__ __nv_bfloat16 g_xh[(size_t)NROWS * DIM];       // LN(x) hi
__device__ __nv_bfloat16 g_xl[(size_t)NROWS * DIM];       // LN(x) lo
__device__ __nv_bfloat16 g_ah[(size_t)NROWS * DIM];       // attn out hi
__device__ __nv_bfloat16 g_al[(size_t)NROWS * DIM];       // attn out lo
__device__ __nv_bfloat16 g_wqkv_h[(size_t)QKVDIM * DIM];  // w_qkv^T hi [N][K]
__device__ __nv_bfloat16 g_wqkv_l[(size_t)QKVDIM * DIM];  // w_qkv^T lo
__device__ __nv_bfloat16 g_wout_h[(size_t)DIM * DIM];     // w_out^T hi
__device__ __nv_bfloat16 g_wout_l[(size_t)DIM * DIM];     // w_out^T lo

// ---------------------------------------------------------------------------
// PTX helpers (baseline PTX only -- harness builds for compute_103)
// ---------------------------------------------------------------------------
__device__ __forceinline__ uint32_t smem_u32(const void* p) {
    uint32_t a;
    asm("{ .reg .u64 t; cvta.to.shared.u64 t, %1; cvt.u32.u64 %0, t; }" : "=r"(a) : "l"(p));
    return a;
}
__device__ __forceinline__ void ldmx4(uint32_t* r, uint32_t addr) {
    asm volatile("ldmatrix.sync.aligned.m8n8.x4.shared.b16 {%0,%1,%2,%3}, [%4];"
        : "=r"(r[0]), "=r"(r[1]), "=r"(r[2]), "=r"(r[3]) : "r"(addr));
}
__device__ __forceinline__ void mma_bf16(float* c, const uint32_t* a, const uint32_t* b) {
    asm volatile(
        "mma.sync.aligned.m16n8k16.row.col.f32.bf16.bf16.f32 "
        "{%0,%1,%2,%3}, {%4,%5,%6,%7}, {%8,%9}, {%0,%1,%2,%3};"
        : "+f"(c[0]), "+f"(c[1]), "+f"(c[2]), "+f"(c[3])
        : "r"(a[0]), "r"(a[1]), "r"(a[2]), "r"(a[3]), "r"(b[0]), "r"(b[1]));
}
#define CP_ASYNC16(dst, src) \
    asm volatile("cp.async.cg.shared.global [%0], [%1], 16;" :: "r"(dst), "l"(src) : "memory")
#define CP_COMMIT() asm volatile("cp.async.commit_group;" ::: "memory")
#define CP_WAIT1()  asm volatile("cp.async.wait_group 1;" ::: "memory")
#define CP_WAIT0()  asm volatile("cp.async.wait_group 0;" ::: "memory")

__device__ __forceinline__ void bf16_split(float v, __nv_bfloat16& h, __nv_bfloat16& l) {
    h = __float2bfloat16_rn(v);
    l = __float2bfloat16_rn(v - __bfloat162float(h));
}

// ---------------------------------------------------------------------------
// Kernel 1: fused LayerNorm + bf16 hi/lo split.  One warp per row of 512.
// ---------------------------------------------------------------------------
__global__ void __launch_bounds__(256) ln_prep_kernel(
    const float* __restrict__ x,
    const float* __restrict__ gamma, const float* __restrict__ beta)
{
    int row  = blockIdx.x * 8 + (threadIdx.x >> 5);
    int lane = threadIdx.x & 31;
    const float4* xp = reinterpret_cast<const float4*>(x + (size_t)row * DIM);
    float4 v[4];
    float s = 0.f, sq = 0.f;
#pragma unroll
    for (int i = 0; i < 4; i++) {
        v[i] = xp[lane + i * 32];
        s  += v[i].x + v[i].y + v[i].z + v[i].w;
        sq += v[i].x * v[i].x + v[i].y * v[i].y + v[i].z * v[i].z + v[i].w * v[i].w;
    }
#pragma unroll
    for (int o = 16; o; o >>= 1) {
        s  += __shfl_xor_sync(0xffffffffu, s,  o);
        sq += __shfl_xor_sync(0xffffffffu, sq, o);
    }
    float m   = s * (1.f / DIM);
    float var = sq * (1.f / DIM) - m * m;
    float rs  = rsqrtf(var + 1e-5f);
#pragma unroll
    for (int i = 0; i < 4; i++) {
        int col = (lane + i * 32) * 4;
        float4 gm = *reinterpret_cast<const float4*>(gamma + col);
        float4 bt = *reinterpret_cast<const float4*>(beta + col);
        float y0 = (v[i].x - m) * rs * gm.x + bt.x;
        float y1 = (v[i].y - m) * rs * gm.y + bt.y;
        float y2 = (v[i].z - m) * rs * gm.z + bt.z;
        float y3 = (v[i].w - m) * rs * gm.w + bt.w;
        __nv_bfloat16 h0, h1, h2, h3, l0, l1, l2, l3;
        bf16_split(y0, h0, l0); bf16_split(y1, h1, l1);
        bf16_split(y2, h2, l2); bf16_split(y3, h3, l3);
        size_t off = (size_t)row * DIM + col;
        *reinterpret_cast<__nv_bfloat162*>(&g_xh[off])     = __nv_bfloat162(h0, h1);
        *reinterpret_cast<__nv_bfloat162*>(&g_xh[off + 2]) = __nv_bfloat162(h2, h3);
        *reinterpret_cast<__nv_bfloat162*>(&g_xl[off])     = __nv_bfloat162(l0, l1);
        *reinterpret_cast<__nv_bfloat162*>(&g_xl[off + 2]) = __nv_bfloat162(l2, l3);
    }
}

// ---------------------------------------------------------------------------
// Kernel 2: transpose weights [K,N] -> [N,K], split to bf16 hi/lo
// ---------------------------------------------------------------------------
__global__ void __launch_bounds__(256) transpose_split_kernel(
    const float* __restrict__ src,
    __nv_bfloat16* __restrict__ dst_h, __nv_bfloat16* __restrict__ dst_l,
    int K, int N)
{
    __shared__ float t[32][33];
    int bx = blockIdx.x * 32;   // n base
    int by = blockIdx.y * 32;   // k base
    int tx = threadIdx.x & 31, ty = threadIdx.x >> 5;
#pragma unroll
    for (int u = 0; u < 4; u++)
        t[ty + u * 8][tx] = src[(size_t)(by + ty + u * 8) * N + bx + tx];
    __syncthreads();
#pragma unroll
    for (int u = 0; u < 4; u++) {
        float val = t[tx][ty + u * 8];
        __nv_bfloat16 h, l;
        bf16_split(val, h, l);
        size_t off = (size_t)(bx + ty + u * 8) * K + by + tx;
        dst_h[off] = h;
        dst_l[off] = l;
    }
}

// ---------------------------------------------------------------------------
// Tensor-core GEMM, pure bf16 operands (hi/lo precomputed in gmem),
// cp.async double-buffered. C = A @ B^T with 3-pass split (hh + hl + lh).
// CTA tile 128x128, K-slab 32, 8 warps (warp tile 64x32), 2 CTAs/SM.
// MODE 0: A = g_xh/g_xl, B = w_qkv^T, C = g_qkv (N=1536)
// MODE 1: A = g_ah/g_al, B = w_out^T, C = out (N=512)
// ---------------------------------------------------------------------------
#define TILE_B   10240u              // 128 rows * 80 B
#define STAGE_B  40960u              // 4 tiles
#define GSMEM    81920               // 2 stages

template <int MODE>
__global__ void __launch_bounds__(256, 2) gemm_mma_kernel(float* __restrict__ Cout)
{
    extern __shared__ char smem[];
    const uint32_t sbase = smem_u32(smem);

    const int N = (MODE == 0) ? QKVDIM : DIM;
    const __nv_bfloat16* __restrict__ Ah = (MODE == 0) ? g_xh : g_ah;
    const __nv_bfloat16* __restrict__ Al = (MODE == 0) ? g_xl : g_al;
    const __nv_bfloat16* __restrict__ Bh = (MODE == 0) ? g_wqkv_h : g_wout_h;
    const __nv_bfloat16* __restrict__ Bl = (MODE == 0) ? g_wqkv_l : g_wout_l;
    float* __restrict__ C = (MODE == 0) ? g_qkv : Cout;

    const int tid  = threadIdx.x;
    const int lane = tid & 31;
    const int wid  = tid >> 5;
    const int bm   = blockIdx.y * 128;
    const int bn   = blockIdx.x * 128;
    const int wm   = (wid & 1) * 64;
    const int wn   = (wid >> 1) * 32;

    float c[4][4][4];
#pragma unroll
    for (int i = 0; i < 4; i++)
#pragma unroll
        for (int j = 0; j < 4; j++)
#pragma unroll
            for (int l = 0; l < 4; l++) c[i][j][l] = 0.f;

    const __nv_bfloat16* srcs[4] = {Ah, Al, Bh, Bl};

    auto issue_stage = [&](int stage, int k0) {
#pragma unroll
        for (int u = 0; u < 8; u++) {
            const int tile = u >> 1;
            int id = tid + u * 256;
            int cch = id & 3;                 // 16B chunk within row (k off = cch*8)
            int r   = (id >> 2) & 127;
            int grow = ((tile < 2) ? bm : bn) + r;
            const void* src = srcs[tile] + (size_t)grow * GK + k0 + cch * 8;
            uint32_t dst = sbase + stage * STAGE_B + tile * TILE_B
                         + (uint32_t)r * 80u + (uint32_t)cch * 16u;
            CP_ASYNC16(dst, src);
        }
        CP_COMMIT();
    };

    issue_stage(0, 0);

    // ldmatrix addressing (same mapping as verified round-4 kernel)
    const int arow = lane & 15;
    const int akof = (lane >> 4) << 3;
    const int brow = (lane & 7) + ((lane >> 4) << 3);
    const int bkof = ((lane >> 3) & 1) << 3;

    for (int it = 0; it < 16; ++it) {
        if (it + 1 < 16) { issue_stage((it + 1) & 1, (it + 1) * 32); CP_WAIT1(); }
        else             { CP_WAIT0(); }
        __syncthreads();

        const uint32_t st = sbase + (uint32_t)(it & 1) * STAGE_B;
        const uint32_t pAh = st;
        const uint32_t pAl = st + TILE_B;
        const uint32_t pBh = st + 2 * TILE_B;
        const uint32_t pBl = st + 3 * TILE_B;

#pragma unroll
        for (int h = 0; h < 2; h++) {         // two k16 halves of the 32-slab
            const uint32_t acol = (uint32_t)(h * 16 + akof) * 2u;
            const uint32_t bcol = (uint32_t)(h * 16 + bkof) * 2u;
            uint32_t ah[4][4], bh[4][2];
#pragma unroll
            for (int mt = 0; mt < 4; mt++)
                ldmx4(ah[mt], pAh + (uint32_t)(wm + mt * 16 + arow) * 80u + acol);
#pragma unroll
            for (int p = 0; p < 2; p++) {
                uint32_t r4[4];
                ldmx4(r4, pBh + (uint32_t)(wn + p * 16 + brow) * 80u + bcol);
                bh[2 * p][0] = r4[0]; bh[2 * p][1] = r4[1];
                bh[2 * p + 1][0] = r4[2]; bh[2 * p + 1][1] = r4[3];
            }
#pragma unroll
            for (int mt = 0; mt < 4; mt++)
#pragma unroll
                for (int nt = 0; nt < 4; nt++) mma_bf16(c[mt][nt], ah[mt], bh[nt]);

            // hi * lo
            uint32_t bl[4][2];
#pragma unroll
            for (int p = 0; p < 2; p++) {
                uint32_t r4[4];
                ldmx4(r4, pBl + (uint32_t)(wn + p * 16 + brow) * 80u + bcol);
                bl[2 * p][0] = r4[0]; bl[2 * p][1] = r4[1];
                bl[2 * p + 1][0] = r4[2]; bl[2 * p + 1][1] = r4[3];
            }
#pragma unroll
            for (int mt = 0; mt < 4; mt++)
#pragma unroll
                for (int nt = 0; nt < 4; nt++) mma_bf16(c[mt][nt], ah[mt], bl[nt]);

            // lo * hi (reuse bl registers for al fragments)
#pragma unroll
            for (int mt = 0; mt < 4; mt++) {
                uint32_t al[4];
                ldmx4(al, pAl + (uint32_t)(wm + mt * 16 + arow) * 80u + acol);
#pragma unroll
                for (int nt = 0; nt < 4; nt++) mma_bf16(c[mt][nt], al, bh[nt]);
            }
        }
        __syncthreads();
    }

    // epilogue: mma C-fragment layout -> gmem (float2 stores)
#pragma unroll
    for (int mt = 0; mt < 4; mt++) {
        int row0 = bm + wm + mt * 16 + (lane >> 2);
#pragma unroll
        for (int nt = 0; nt < 4; nt++) {
            int col = bn + wn + nt * 8 + (lane & 3) * 2;
            *reinterpret_cast<float2*>(C + (size_t)row0 * N + col)
                = make_float2(c[mt][nt][0], c[mt][nt][1]);
            *reinterpret_cast<float2*>(C + (size_t)(row0 + 8) * N + col)
                = make_float2(c[mt][nt][2], c[mt][nt][3]);
        }
    }
}

// ---------------------------------------------------------------------------
// Kernel: windowed attention, one block per (window, head).
// Output written directly as bf16 hi/lo (feeds out-proj GEMM).
// ---------------------------------------------------------------------------
__global__ void __launch_bounds__(128) attn_kernel(
    const float* __restrict__ mem_kv,
    const float* __restrict__ rel_bias,
    const int*   __restrict__ rel_idx)
{
    const int w = blockIdx.x;
    const int h = blockIdx.y;
    const int tid = threadIdx.x;

    __shared__ float q_s[NTOK][36];
    __shared__ float k_s[NCTX][36];
    __shared__ float v_s[NCTX][36];
    __shared__ float sim[NTOK][NCTX];

    const size_t base = (size_t)w * NTOK * QKVDIM;
    const int hcol = h * DH;

    for (int idx = tid; idx < NTOK * DH; idx += 128) {
        int i = idx >> 5, d = idx & 31;
        q_s[i][d] = g_qkv[base + (size_t)i * QKVDIM + hcol + d];
    }
    for (int idx = tid; idx < NCTX * DH; idx += 128) {
        int j = idx >> 5, d = idx & 31;
        if (j < NMEM) {
            k_s[j][d] = mem_kv[(h * NMEM + j) * DH + d];
            v_s[j][d] = mem_kv[NHEAD * NMEM * DH + (h * NMEM + j) * DH + d];
        } else {
            size_t rb = base + (size_t)(j - NMEM) * QKVDIM + hcol + d;
            k_s[j][d] = g_qkv[rb + DIM];
            v_s[j][d] = g_qkv[rb + 2 * DIM];
        }
    }
    __syncthreads();

    const float scale = 0.17677669529663687f;  // 1/sqrt(32)
    for (int idx = tid; idx < NTOK * NCTX; idx += 128) {
        int i = idx / NCTX;
        int j = idx - i * NCTX;
        const float4* qp = reinterpret_cast<const float4*>(q_s[i]);
        const float4* kp = reinterpret_cast<const float4*>(k_s[j]);
        float acc = 0.f;
#pragma unroll
        for (int c = 0; c < 8; c++) {
            float4 a = qp[c], b = kp[c];
            acc += a.x * b.x + a.y * b.y + a.z * b.z + a.w * b.w;
        }
        float bias = 0.f;
        if (j >= NMEM) bias = rel_bias[rel_idx[i * NTOK + (j - NMEM)] * NHEAD + h];
        sim[i][j] = acc * scale + bias;
    }
    __syncthreads();

    const int wp = tid >> 5, lane = tid & 31;
    for (int i = wp; i < NTOK; i += 4) {
        float s0 = sim[i][lane];
        float s1 = (lane < NCTX - 32) ? sim[i][lane + 32] : -1e30f;
        float m = fmaxf(s0, s1);
#pragma unroll
        for (int o = 16; o; o >>= 1) m = fmaxf(m, __shfl_xor_sync(0xffffffffu, m, o));
        float e0 = __expf(s0 - m);
        float e1 = (lane < NCTX - 32) ? __expf(s1 - m) : 0.f;
        float s = e0 + e1;
#pragma unroll
        for (int o = 16; o; o >>= 1) s += __shfl_xor_sync(0xffffffffu, s, o);
        float inv = 1.f / s;
        sim[i][lane] = e0 * inv;
        if (lane < NCTX - 32) sim[i][lane + 32] = e1 * inv;
    }
    __syncthreads();

    for (int idx = tid; idx < NTOK * DH; idx += 128) {
        int i = idx >> 5, d = idx & 31;
        float acc = 0.f;
#pragma unroll
        for (int j = 0; j < NCTX; j++) acc += sim[i][j] * v_s[j][d];
        __nv_bfloat16 hh, ll;
        bf16_split(acc, hh, ll);
        size_t off = ((size_t)w * NTOK + i) * DIM + hcol + d;
        g_ah[off] = hh;
        g_al[off] = ll;
    }
}

// ---------------------------------------------------------------------------
// Launch
// ---------------------------------------------------------------------------
extern "C" void kernel_launch(void* const* d_in, const int* in_sizes, int n_in,
                              void* d_out, int out_size) {
    const float* x        = (const float*)d_in[0];
    const float* ln_gamma = (const float*)d_in[1];
    const float* ln_beta  = (const float*)d_in[2];
    const float* w_qkv    = (const float*)d_in[3];
    const float* mem_kv   = (const float*)d_in[4];
    const float* w_out    = (const float*)d_in[5];
    const float* rel_bias = (const float*)d_in[6];
    const int*   rel_idx  = (const int*)d_in[7];
    float* out = (float*)d_out;

    static bool attr_set = false;
    if (!attr_set) {
        cudaFuncSetAttribute(gemm_mma_kernel<0>, cudaFuncAttributeMaxDynamicSharedMemorySize, GSMEM);
        cudaFuncSetAttribute(gemm_mma_kernel<1>, cudaFuncAttributeMaxDynamicSharedMemorySize, GSMEM);
        attr_set = true;
    }

    __nv_bfloat16 *wqh, *wql, *woh, *wol;
    cudaGetSymbolAddress((void**)&wqh, g_wqkv_h);
    cudaGetSymbolAddress((void**)&wql, g_wqkv_l);
    cudaGetSymbolAddress((void**)&woh, g_wout_h);
    cudaGetSymbolAddress((void**)&wol, g_wout_l);

    // 1) fused LN + hi/lo split
    ln_prep_kernel<<<NROWS / 8, 256>>>(x, ln_gamma, ln_beta);

    // 2) weight transpose + split (tiny)
    transpose_split_kernel<<<dim3(QKVDIM / 32, DIM / 32), 256>>>(w_qkv, wqh, wql, DIM, QKVDIM);
    transpose_split_kernel<<<dim3(DIM / 32, DIM / 32), 256>>>(w_out, woh, wol, DIM, DIM);

    // 3) QKV GEMM (tensor cores): g_qkv = LN(x) @ w_qkv
    gemm_mma_kernel<0><<<dim3(QKVDIM / 128, NROWS / 128), 256, GSMEM>>>(nullptr);

    // 4) windowed attention per (window, head) -> g_ah/g_al (bf16 split)
    attn_kernel<<<dim3(NWIN, NHEAD), 128>>>(mem_kv, rel_bias, rel_idx);

    // 5) output projection (tensor cores): out = attn_out @ w_out
    gemm_mma_kernel<1><<<dim3(DIM / 128, NROWS / 128), 256, GSMEM>>>(out);
}

// round 6
// speedup vs baseline: 2.6188x; 1.4333x over previous
#include <cuda_runtime.h>
#include <cuda_fp16.h>
#include <cstdint>

// Problem constants
#define NROWS   100352        // 2048 windows * 49 tokens
#define DIM     512
#define QKVDIM  1536
#define NWIN    2048
#define NTOK    49
#define NHEAD   16
#define DH      32
#define NMEM    4
#define NCTX    53            // NMEM + NTOK
#define GK      512           // GEMM K (both GEMMs)

// ---------------------------------------------------------------------------
// Scratch (device globals: no allocation allowed anywhere)
// ---------------------------------------------------------------------------
__device__ float g_qkv[(size_t)NROWS * QKVDIM];       // 616 MB fp32
__device__ __half g_xh[(size_t)NROWS * DIM];          // LN(x) fp16
__device__ __half g_ah[(size_t)NROWS * DIM];          // attn out fp16
__device__ __half g_wqkv_h[(size_t)QKVDIM * DIM];     // w_qkv^T fp16 [N][K]
__device__ __half g_wout_h[(size_t)DIM * DIM];        // w_out^T fp16 [N][K]

// ---------------------------------------------------------------------------
// PTX helpers (baseline PTX only -- harness builds for compute_103)
// ---------------------------------------------------------------------------
__device__ __forceinline__ uint32_t smem_u32(const void* p) {
    uint32_t a;
    asm("{ .reg .u64 t; cvta.to.shared.u64 t, %1; cvt.u32.u64 %0, t; }" : "=r"(a) : "l"(p));
    return a;
}
__device__ __forceinline__ void ldmx4(uint32_t* r, uint32_t addr) {
    asm volatile("ldmatrix.sync.aligned.m8n8.x4.shared.b16 {%0,%1,%2,%3}, [%4];"
        : "=r"(r[0]), "=r"(r[1]), "=r"(r[2]), "=r"(r[3]) : "r"(addr));
}
__device__ __forceinline__ void mma_f16(float* c, const uint32_t* a, const uint32_t* b) {
    asm volatile(
        "mma.sync.aligned.m16n8k16.row.col.f32.f16.f16.f32 "
        "{%0,%1,%2,%3}, {%4,%5,%6,%7}, {%8,%9}, {%0,%1,%2,%3};"
        : "+f"(c[0]), "+f"(c[1]), "+f"(c[2]), "+f"(c[3])
        : "r"(a[0]), "r"(a[1]), "r"(a[2]), "r"(a[3]), "r"(b[0]), "r"(b[1]));
}
#define CP_ASYNC16(dst, src) \
    asm volatile("cp.async.cg.shared.global [%0], [%1], 16;" :: "r"(dst), "l"(src) : "memory")
#define CP_COMMIT() asm volatile("cp.async.commit_group;" ::: "memory")
#define CP_WAIT1()  asm volatile("cp.async.wait_group 1;" ::: "memory")
#define CP_WAIT0()  asm volatile("cp.async.wait_group 0;" ::: "memory")

// ---------------------------------------------------------------------------
// Kernel 1: fused LayerNorm -> fp16.  One warp per row of 512.
// ---------------------------------------------------------------------------
__global__ void __launch_bounds__(256) ln_prep_kernel(
    const float* __restrict__ x,
    const float* __restrict__ gamma, const float* __restrict__ beta)
{
    int row  = blockIdx.x * 8 + (threadIdx.x >> 5);
    int lane = threadIdx.x & 31;
    const float4* xp = reinterpret_cast<const float4*>(x + (size_t)row * DIM);
    float4 v[4];
    float s = 0.f, sq = 0.f;
#pragma unroll
    for (int i = 0; i < 4; i++) {
        v[i] = xp[lane + i * 32];
        s  += v[i].x + v[i].y + v[i].z + v[i].w;
        sq += v[i].x * v[i].x + v[i].y * v[i].y + v[i].z * v[i].z + v[i].w * v[i].w;
    }
#pragma unroll
    for (int o = 16; o; o >>= 1) {
        s  += __shfl_xor_sync(0xffffffffu, s,  o);
        sq += __shfl_xor_sync(0xffffffffu, sq, o);
    }
    float m   = s * (1.f / DIM);
    float var = sq * (1.f / DIM) - m * m;
    float rs  = rsqrtf(var + 1e-5f);
#pragma unroll
    for (int i = 0; i < 4; i++) {
        int col = (lane + i * 32) * 4;
        float4 gm = *reinterpret_cast<const float4*>(gamma + col);
        float4 bt = *reinterpret_cast<const float4*>(beta + col);
        float y0 = (v[i].x - m) * rs * gm.x + bt.x;
        float y1 = (v[i].y - m) * rs * gm.y + bt.y;
        float y2 = (v[i].z - m) * rs * gm.z + bt.z;
        float y3 = (v[i].w - m) * rs * gm.w + bt.w;
        size_t off = (size_t)row * DIM + col;
        __half2* hp = reinterpret_cast<__half2*>(&g_xh[off]);
        hp[0] = __floats2half2_rn(y0, y1);
        hp[1] = __floats2half2_rn(y2, y3);
    }
}

// ---------------------------------------------------------------------------
// Kernel 2: transpose weights [K,N] -> [N,K] fp16
// ---------------------------------------------------------------------------
__global__ void __launch_bounds__(256) transpose_h_kernel(
    const float* __restrict__ src, __half* __restrict__ dst, int K, int N)
{
    __shared__ float t[32][33];
    int bx = blockIdx.x * 32;   // n base
    int by = blockIdx.y * 32;   // k base
    int tx = threadIdx.x & 31, ty = threadIdx.x >> 5;
#pragma unroll
    for (int u = 0; u < 4; u++)
        t[ty + u * 8][tx] = src[(size_t)(by + ty + u * 8) * N + bx + tx];
    __syncthreads();
#pragma unroll
    for (int u = 0; u < 4; u++)
        dst[(size_t)(bx + ty + u * 8) * K + by + tx] = __float2half_rn(t[tx][ty + u * 8]);
}

// ---------------------------------------------------------------------------
// Tensor-core GEMM, fp16 operands, single pass, cp.async double-buffered.
// CTA tile 128x128, K-slab 32, 8 warps (warp tile 64x32), 2 CTAs/SM.
// MODE 0: A = g_xh, B = w_qkv^T, C = g_qkv (N=1536)
// MODE 1: A = g_ah, B = w_out^T, C = out (N=512)
// ---------------------------------------------------------------------------
#define TILE_B   10240u              // 128 rows * 80 B
#define STAGE_B  20480u              // 2 tiles (A,B)
#define GSMEM    40960               // 2 stages

template <int MODE>
__global__ void __launch_bounds__(256, 2) gemm_mma_kernel(float* __restrict__ Cout)
{
    extern __shared__ char smem[];
    const uint32_t sbase = smem_u32(smem);

    const int N = (MODE == 0) ? QKVDIM : DIM;
    const __half* __restrict__ Ah = (MODE == 0) ? g_xh : g_ah;
    const __half* __restrict__ Bh = (MODE == 0) ? g_wqkv_h : g_wout_h;
    float* __restrict__ C = (MODE == 0) ? g_qkv : Cout;

    const int tid  = threadIdx.x;
    const int lane = tid & 31;
    const int wid  = tid >> 5;
    const int bm   = blockIdx.y * 128;
    const int bn   = blockIdx.x * 128;
    const int wm   = (wid & 1) * 64;
    const int wn   = (wid >> 1) * 32;

    float c[4][4][4];
#pragma unroll
    for (int i = 0; i < 4; i++)
#pragma unroll
        for (int j = 0; j < 4; j++)
#pragma unroll
            for (int l = 0; l < 4; l++) c[i][j][l] = 0.f;

    auto issue_stage = [&](int stage, int k0) {
#pragma unroll
        for (int u = 0; u < 4; u++) {
            const int tile = u >> 1;          // 0 = A, 1 = B
            int id = tid + u * 256;
            int cch = id & 3;                 // 16B chunk (k off = cch*8)
            int r   = (id >> 2) & 127;
            int grow = ((tile == 0) ? bm : bn) + r;
            const void* src = ((tile == 0) ? Ah : Bh) + (size_t)grow * GK + k0 + cch * 8;
            uint32_t dst = sbase + stage * STAGE_B + tile * TILE_B
                         + (uint32_t)r * 80u + (uint32_t)cch * 16u;
            CP_ASYNC16(dst, src);
        }
        CP_COMMIT();
    };

    issue_stage(0, 0);

    const int arow = lane & 15;
    const int akof = (lane >> 4) << 3;
    const int brow = (lane & 7) + ((lane >> 4) << 3);
    const int bkof = ((lane >> 3) & 1) << 3;

    for (int it = 0; it < 16; ++it) {
        if (it + 1 < 16) { issue_stage((it + 1) & 1, (it + 1) * 32); CP_WAIT1(); }
        else             { CP_WAIT0(); }
        __syncthreads();

        const uint32_t st  = sbase + (uint32_t)(it & 1) * STAGE_B;
        const uint32_t pAh = st;
        const uint32_t pBh = st + TILE_B;

#pragma unroll
        for (int h = 0; h < 2; h++) {         // two k16 halves of the 32-slab
            const uint32_t acol = (uint32_t)(h * 16 + akof) * 2u;
            const uint32_t bcol = (uint32_t)(h * 16 + bkof) * 2u;
            uint32_t ah[4][4], bh[4][2];
#pragma unroll
            for (int mt = 0; mt < 4; mt++)
                ldmx4(ah[mt], pAh + (uint32_t)(wm + mt * 16 + arow) * 80u + acol);
#pragma unroll
            for (int p = 0; p < 2; p++) {
                uint32_t r4[4];
                ldmx4(r4, pBh + (uint32_t)(wn + p * 16 + brow) * 80u + bcol);
                bh[2 * p][0] = r4[0]; bh[2 * p][1] = r4[1];
                bh[2 * p + 1][0] = r4[2]; bh[2 * p + 1][1] = r4[3];
            }
#pragma unroll
            for (int mt = 0; mt < 4; mt++)
#pragma unroll
                for (int nt = 0; nt < 4; nt++) mma_f16(c[mt][nt], ah[mt], bh[nt]);
        }
        __syncthreads();
    }

    // epilogue: mma C-fragment layout -> gmem (float2 stores)
#pragma unroll
    for (int mt = 0; mt < 4; mt++) {
        int row0 = bm + wm + mt * 16 + (lane >> 2);
#pragma unroll
        for (int nt = 0; nt < 4; nt++) {
            int col = bn + wn + nt * 8 + (lane & 3) * 2;
            *reinterpret_cast<float2*>(C + (size_t)row0 * N + col)
                = make_float2(c[mt][nt][0], c[mt][nt][1]);
            *reinterpret_cast<float2*>(C + (size_t)(row0 + 8) * N + col)
                = make_float2(c[mt][nt][2], c[mt][nt][3]);
        }
    }
}

// ---------------------------------------------------------------------------
// Kernel: windowed attention, one block per (window, head).
// Output written as fp16 (feeds out-proj GEMM).
// ---------------------------------------------------------------------------
__global__ void __launch_bounds__(128) attn_kernel(
    const float* __restrict__ mem_kv,
    const float* __restrict__ rel_bias,
    const int*   __restrict__ rel_idx)
{
    const int w = blockIdx.x;
    const int h = blockIdx.y;
    const int tid = threadIdx.x;

    __shared__ float q_s[NTOK][36];
    __shared__ float k_s[NCTX][36];
    __shared__ float v_s[NCTX][36];
    __shared__ float sim[NTOK][NCTX];

    const size_t base = (size_t)w * NTOK * QKVDIM;
    const int hcol = h * DH;

    for (int idx = tid; idx < NTOK * DH; idx += 128) {
        int i = idx >> 5, d = idx & 31;
        q_s[i][d] = g_qkv[base + (size_t)i * QKVDIM + hcol + d];
    }
    for (int idx = tid; idx < NCTX * DH; idx += 128) {
        int j = idx >> 5, d = idx & 31;
        if (j < NMEM) {
            k_s[j][d] = mem_kv[(h * NMEM + j) * DH + d];
            v_s[j][d] = mem_kv[NHEAD * NMEM * DH + (h * NMEM + j) * DH + d];
        } else {
            size_t rb = base + (size_t)(j - NMEM) * QKVDIM + hcol + d;
            k_s[j][d] = g_qkv[rb + DIM];
            v_s[j][d] = g_qkv[rb + 2 * DIM];
        }
    }
    __syncthreads();

    const float scale = 0.17677669529663687f;  // 1/sqrt(32)
    for (int idx = tid; idx < NTOK * NCTX; idx += 128) {
        int i = idx / NCTX;
        int j = idx - i * NCTX;
        const float4* qp = reinterpret_cast<const float4*>(q_s[i]);
        const float4* kp = reinterpret_cast<const float4*>(k_s[j]);
        float acc = 0.f;
#pragma unroll
        for (int c = 0; c < 8; c++) {
            float4 a = qp[c], b = kp[c];
            acc += a.x * b.x + a.y * b.y + a.z * b.z + a.w * b.w;
        }
        float bias = 0.f;
        if (j >= NMEM) bias = rel_bias[rel_idx[i * NTOK + (j - NMEM)] * NHEAD + h];
        sim[i][j] = acc * scale + bias;
    }
    __syncthreads();

    const int wp = tid >> 5, lane = tid & 31;
    for (int i = wp; i < NTOK; i += 4) {
        float s0 = sim[i][lane];
        float s1 = (lane < NCTX - 32) ? sim[i][lane + 32] : -1e30f;
        float m = fmaxf(s0, s1);
#pragma unroll
        for (int o = 16; o; o >>= 1) m = fmaxf(m, __shfl_xor_sync(0xffffffffu, m, o));
        float e0 = __expf(s0 - m);
        float e1 = (lane < NCTX - 32) ? __expf(s1 - m) : 0.f;
        float s = e0 + e1;
#pragma unroll
        for (int o = 16; o; o >>= 1) s += __shfl_xor_sync(0xffffffffu, s, o);
        float inv = 1.f / s;
        sim[i][lane] = e0 * inv;
        if (lane < NCTX - 32) sim[i][lane + 32] = e1 * inv;
    }
    __syncthreads();

    for (int idx = tid; idx < NTOK * DH; idx += 128) {
        int i = idx >> 5, d = idx & 31;
        float acc = 0.f;
#pragma unroll
        for (int j = 0; j < NCTX; j++) acc += sim[i][j] * v_s[j][d];
        g_ah[((size_t)w * NTOK + i) * DIM + hcol + d] = __float2half_rn(acc);
    }
}

// ---------------------------------------------------------------------------
// Launch
// ---------------------------------------------------------------------------
extern "C" void kernel_launch(void* const* d_in, const int* in_sizes, int n_in,
                              void* d_out, int out_size) {
    const float* x        = (const float*)d_in[0];
    const float* ln_gamma = (const float*)d_in[1];
    const float* ln_beta  = (const float*)d_in[2];
    const float* w_qkv    = (const float*)d_in[3];
    const float* mem_kv   = (const float*)d_in[4];
    const float* w_out    = (const float*)d_in[5];
    const float* rel_bias = (const float*)d_in[6];
    const int*   rel_idx  = (const int*)d_in[7];
    float* out = (float*)d_out;

    static bool attr_set = false;
    if (!attr_set) {
        cudaFuncSetAttribute(gemm_mma_kernel<0>, cudaFuncAttributeMaxDynamicSharedMemorySize, GSMEM);
        cudaFuncSetAttribute(gemm_mma_kernel<1>, cudaFuncAttributeMaxDynamicSharedMemorySize, GSMEM);
        attr_set = true;
    }

    __half *wqh, *woh;
    cudaGetSymbolAddress((void**)&wqh, g_wqkv_h);
    cudaGetSymbolAddress((void**)&woh, g_wout_h);

    // 1) fused LN -> fp16
    ln_prep_kernel<<<NROWS / 8, 256>>>(x, ln_gamma, ln_beta);

    // 2) weight transpose -> fp16 (tiny)
    transpose_h_kernel<<<dim3(QKVDIM / 32, DIM / 32), 256>>>(w_qkv, wqh, DIM, QKVDIM);
    transpose_h_kernel<<<dim3(DIM / 32, DIM / 32), 256>>>(w_out, woh, DIM, DIM);

    // 3) QKV GEMM (tensor cores): g_qkv = LN(x) @ w_qkv
    gemm_mma_kernel<0><<<dim3(QKVDIM / 128, NROWS / 128), 256, GSMEM>>>(nullptr);

    // 4) windowed attention per (window, head) -> g_ah (fp16)
    attn_kernel<<<dim3(NWIN, NHEAD), 128>>>(mem_kv, rel_bias, rel_idx);

    // 5) output projection (tensor cores): out = attn_out @ w_out
    gemm_mma_kernel<1><<<dim3(DIM / 128, NROWS / 128), 256, GSMEM>>>(out);
}

// round 7
// speedup vs baseline: 5.6345x; 2.1515x over previous
#include <cuda_runtime.h>
#include <cuda_fp16.h>
#include <cstdint>

// Problem constants
#define NROWS   100352        // 2048 windows * 49 tokens
#define DIM     512
#define QKVDIM  1536
#define NWIN    2048
#define NTOK    49
#define NHEAD   16
#define DH      32
#define NMEM    4
#define NCTX    53            // NMEM + NTOK
#define GK      512           // GEMM K (both GEMMs)

// ---------------------------------------------------------------------------
// Scratch (device globals: no allocation allowed anywhere)
// ---------------------------------------------------------------------------
__device__ __half g_qkv[(size_t)NROWS * QKVDIM];      // 308 MB fp16
__device__ __half g_xh[(size_t)NROWS * DIM];          // LN(x) fp16
__device__ __half g_ah[(size_t)NROWS * DIM];          // attn out fp16
__device__ __half g_wqkv_h[(size_t)QKVDIM * DIM];     // w_qkv^T fp16 [N][K]
__device__ __half g_wout_h[(size_t)DIM * DIM];        // w_out^T fp16 [N][K]
__device__ float  g_bias[16 * 49 * 64];               // per-head bias, 64-padded cols

// ---------------------------------------------------------------------------
// PTX helpers (baseline PTX only -- harness builds for compute_103)
// ---------------------------------------------------------------------------
__device__ __forceinline__ uint32_t smem_u32(const void* p) {
    uint32_t a;
    asm("{ .reg .u64 t; cvta.to.shared.u64 t, %1; cvt.u32.u64 %0, t; }" : "=r"(a) : "l"(p));
    return a;
}
__device__ __forceinline__ void ldmx4(uint32_t* r, uint32_t addr) {
    asm volatile("ldmatrix.sync.aligned.m8n8.x4.shared.b16 {%0,%1,%2,%3}, [%4];"
        : "=r"(r[0]), "=r"(r[1]), "=r"(r[2]), "=r"(r[3]) : "r"(addr));
}
__device__ __forceinline__ void ldmx4t(uint32_t* r, uint32_t addr) {
    asm volatile("ldmatrix.sync.aligned.m8n8.x4.trans.shared.b16 {%0,%1,%2,%3}, [%4];"
        : "=r"(r[0]), "=r"(r[1]), "=r"(r[2]), "=r"(r[3]) : "r"(addr));
}
__device__ __forceinline__ void mma_f16(float* c, const uint32_t* a, const uint32_t* b) {
    asm volatile(
        "mma.sync.aligned.m16n8k16.row.col.f32.f16.f16.f32 "
        "{%0,%1,%2,%3}, {%4,%5,%6,%7}, {%8,%9}, {%0,%1,%2,%3};"
        : "+f"(c[0]), "+f"(c[1]), "+f"(c[2]), "+f"(c[3])
        : "r"(a[0]), "r"(a[1]), "r"(a[2]), "r"(a[3]), "r"(b[0]), "r"(b[1]));
}
__device__ __forceinline__ uint32_t packh2(float a, float b) {
    __half2 t = __floats2half2_rn(a, b);
    return *reinterpret_cast<uint32_t*>(&t);
}
#define CP_ASYNC16(dst, src) \
    asm volatile("cp.async.cg.shared.global [%0], [%1], 16;" :: "r"(dst), "l"(src) : "memory")
#define CP_COMMIT() asm volatile("cp.async.commit_group;" ::: "memory")
#define CP_WAIT1()  asm volatile("cp.async.wait_group 1;" ::: "memory")
#define CP_WAIT0()  asm volatile("cp.async.wait_group 0;" ::: "memory")

// ---------------------------------------------------------------------------
// Kernel 1: fused LayerNorm -> fp16.  One warp per row of 512.
// ---------------------------------------------------------------------------
__global__ void __launch_bounds__(256) ln_prep_kernel(
    const float* __restrict__ x,
    const float* __restrict__ gamma, const float* __restrict__ beta)
{
    int row  = blockIdx.x * 8 + (threadIdx.x >> 5);
    int lane = threadIdx.x & 31;
    const float4* xp = reinterpret_cast<const float4*>(x + (size_t)row * DIM);
    float4 v[4];
    float s = 0.f, sq = 0.f;
#pragma unroll
    for (int i = 0; i < 4; i++) {
        v[i] = xp[lane + i * 32];
        s  += v[i].x + v[i].y + v[i].z + v[i].w;
        sq += v[i].x * v[i].x + v[i].y * v[i].y + v[i].z * v[i].z + v[i].w * v[i].w;
    }
#pragma unroll
    for (int o = 16; o; o >>= 1) {
        s  += __shfl_xor_sync(0xffffffffu, s,  o);
        sq += __shfl_xor_sync(0xffffffffu, sq, o);
    }
    float m   = s * (1.f / DIM);
    float var = sq * (1.f / DIM) - m * m;
    float rs  = rsqrtf(var + 1e-5f);
#pragma unroll
    for (int i = 0; i < 4; i++) {
        int col = (lane + i * 32) * 4;
        float4 gm = *reinterpret_cast<const float4*>(gamma + col);
        float4 bt = *reinterpret_cast<const float4*>(beta + col);
        float y0 = (v[i].x - m) * rs * gm.x + bt.x;
        float y1 = (v[i].y - m) * rs * gm.y + bt.y;
        float y2 = (v[i].z - m) * rs * gm.z + bt.z;
        float y3 = (v[i].w - m) * rs * gm.w + bt.w;
        size_t off = (size_t)row * DIM + col;
        __half2* hp = reinterpret_cast<__half2*>(&g_xh[off]);
        hp[0] = __floats2half2_rn(y0, y1);
        hp[1] = __floats2half2_rn(y2, y3);
    }
}

// ---------------------------------------------------------------------------
// Kernel 2: transpose weights [K,N] -> [N,K] fp16
// ---------------------------------------------------------------------------
__global__ void __launch_bounds__(256) transpose_h_kernel(
    const float* __restrict__ src, __half* __restrict__ dst, int K, int N)
{
    __shared__ float t[32][33];
    int bx = blockIdx.x * 32;   // n base
    int by = blockIdx.y * 32;   // k base
    int tx = threadIdx.x & 31, ty = threadIdx.x >> 5;
#pragma unroll
    for (int u = 0; u < 4; u++)
        t[ty + u * 8][tx] = src[(size_t)(by + ty + u * 8) * N + bx + tx];
    __syncthreads();
#pragma unroll
    for (int u = 0; u < 4; u++)
        dst[(size_t)(bx + ty + u * 8) * K + by + tx] = __float2half_rn(t[tx][ty + u * 8]);
}

// ---------------------------------------------------------------------------
// Kernel 3: per-head bias table  g_bias[h][i][j] (j 64-padded, mem cols = 0)
// ---------------------------------------------------------------------------
__global__ void __launch_bounds__(256) bias_prep_kernel(
    const float* __restrict__ rel_bias, const int* __restrict__ rel_idx)
{
    int idx = blockIdx.x * 256 + threadIdx.x;
    if (idx >= 16 * 49 * 64) return;
    int h = idx / (49 * 64);
    int rem = idx - h * 49 * 64;
    int i = rem >> 6;
    int j = rem & 63;
    float v = 0.f;
    if (j >= NMEM && j < NCTX)
        v = rel_bias[rel_idx[i * NTOK + (j - NMEM)] * NHEAD + h];
    g_bias[idx] = v;
}

// ---------------------------------------------------------------------------
// Tensor-core GEMM, fp16 operands, single pass, cp.async double-buffered.
// CTA tile 128x128, K-slab 32, 8 warps (warp tile 64x32), 2 CTAs/SM.
// MODE 0: A = g_xh, B = w_qkv^T, C = g_qkv (fp16, N=1536)
// MODE 1: A = g_ah, B = w_out^T, C = out (fp32, N=512)
// ---------------------------------------------------------------------------
#define TILE_B   10240u              // 128 rows * 80 B
#define STAGE_B  20480u              // 2 tiles (A,B)
#define GSMEM    40960               // 2 stages

template <int MODE>
__global__ void __launch_bounds__(256, 2) gemm_mma_kernel(float* __restrict__ Cout)
{
    extern __shared__ char smem[];
    const uint32_t sbase = smem_u32(smem);

    const int N = (MODE == 0) ? QKVDIM : DIM;
    const __half* __restrict__ Ah = (MODE == 0) ? g_xh : g_ah;
    const __half* __restrict__ Bh = (MODE == 0) ? g_wqkv_h : g_wout_h;

    const int tid  = threadIdx.x;
    const int lane = tid & 31;
    const int wid  = tid >> 5;
    const int bm   = blockIdx.y * 128;
    const int bn   = blockIdx.x * 128;
    const int wm   = (wid & 1) * 64;
    const int wn   = (wid >> 1) * 32;

    float c[4][4][4];
#pragma unroll
    for (int i = 0; i < 4; i++)
#pragma unroll
        for (int j = 0; j < 4; j++)
#pragma unroll
            for (int l = 0; l < 4; l++) c[i][j][l] = 0.f;

    auto issue_stage = [&](int stage, int k0) {
#pragma unroll
        for (int u = 0; u < 4; u++) {
            const int tile = u >> 1;          // 0 = A, 1 = B
            int id = tid + u * 256;
            int cch = id & 3;                 // 16B chunk (k off = cch*8)
            int r   = (id >> 2) & 127;
            int grow = ((tile == 0) ? bm : bn) + r;
            const void* src = ((tile == 0) ? Ah : Bh) + (size_t)grow * GK + k0 + cch * 8;
            uint32_t dst = sbase + stage * STAGE_B + tile * TILE_B
                         + (uint32_t)r * 80u + (uint32_t)cch * 16u;
            CP_ASYNC16(dst, src);
        }
        CP_COMMIT();
    };

    issue_stage(0, 0);

    const int arow = lane & 15;
    const int akof = (lane >> 4) << 3;
    const int brow = (lane & 7) + ((lane >> 4) << 3);
    const int bkof = ((lane >> 3) & 1) << 3;

    for (int it = 0; it < 16; ++it) {
        if (it + 1 < 16) { issue_stage((it + 1) & 1, (it + 1) * 32); CP_WAIT1(); }
        else             { CP_WAIT0(); }
        __syncthreads();

        const uint32_t st  = sbase + (uint32_t)(it & 1) * STAGE_B;
        const uint32_t pAh = st;
        const uint32_t pBh = st + TILE_B;

#pragma unroll
        for (int h = 0; h < 2; h++) {
            const uint32_t acol = (uint32_t)(h * 16 + akof) * 2u;
            const uint32_t bcol = (uint32_t)(h * 16 + bkof) * 2u;
            uint32_t ah[4][4], bh[4][2];
#pragma unroll
            for (int mt = 0; mt < 4; mt++)
                ldmx4(ah[mt], pAh + (uint32_t)(wm + mt * 16 + arow) * 80u + acol);
#pragma unroll
            for (int p = 0; p < 2; p++) {
                uint32_t r4[4];
                ldmx4(r4, pBh + (uint32_t)(wn + p * 16 + brow) * 80u + bcol);
                bh[2 * p][0] = r4[0]; bh[2 * p][1] = r4[1];
                bh[2 * p + 1][0] = r4[2]; bh[2 * p + 1][1] = r4[3];
            }
#pragma unroll
            for (int mt = 0; mt < 4; mt++)
#pragma unroll
                for (int nt = 0; nt < 4; nt++) mma_f16(c[mt][nt], ah[mt], bh[nt]);
        }
        __syncthreads();
    }

    // epilogue
#pragma unroll
    for (int mt = 0; mt < 4; mt++) {
        int row0 = bm + wm + mt * 16 + (lane >> 2);
#pragma unroll
        for (int nt = 0; nt < 4; nt++) {
            int col = bn + wn + nt * 8 + (lane & 3) * 2;
            if (MODE == 0) {
                *reinterpret_cast<__half2*>(&g_qkv[(size_t)row0 * N + col])
                    = __floats2half2_rn(c[mt][nt][0], c[mt][nt][1]);
                *reinterpret_cast<__half2*>(&g_qkv[(size_t)(row0 + 8) * N + col])
                    = __floats2half2_rn(c[mt][nt][2], c[mt][nt][3]);
            } else {
                *reinterpret_cast<float2*>(Cout + (size_t)row0 * N + col)
                    = make_float2(c[mt][nt][0], c[mt][nt][1]);
                *reinterpret_cast<float2*>(Cout + (size_t)(row0 + 8) * N + col)
                    = make_float2(c[mt][nt][2], c[mt][nt][3]);
            }
        }
    }
}

// ---------------------------------------------------------------------------
// Kernel: tensor-core windowed attention, one block (4 warps) per (window, head).
// M padded to 64 (4 warp m-tiles of 16), ctx padded to 64 (8 n-tiles).
// QK mma -> fp32 softmax in regs -> P as fp16 A-frags -> PV mma (V via ldmatrix.trans).
// ---------------------------------------------------------------------------
__global__ void __launch_bounds__(128) attn_kernel(const float* __restrict__ mem_kv)
{
    const int w = blockIdx.x;
    const int h = blockIdx.y;
    const int tid = threadIdx.x;
    const int lane = tid & 31;
    const int wid = tid >> 5;

    __shared__ alignas(16) __half qs[64][40];
    __shared__ alignas(16) __half ks[64][40];
    __shared__ alignas(16) __half vs[64][40];

    // zero-pad all tiles (rows beyond valid range must be 0)
    {
        uint4 z = make_uint4(0, 0, 0, 0);
        uint4* q4 = reinterpret_cast<uint4*>(&qs[0][0]);
        uint4* k4 = reinterpret_cast<uint4*>(&ks[0][0]);
        uint4* v4 = reinterpret_cast<uint4*>(&vs[0][0]);
        for (int i = tid; i < 320; i += 128) { q4[i] = z; k4[i] = z; v4[i] = z; }
    }
    __syncthreads();

    // fill q (rows 0..48), k/v (rows 4..52 from qkv, rows 0..3 from mem_kv)
    const __half* qbase = g_qkv + (size_t)w * NTOK * QKVDIM + h * DH;
    for (int idx = tid; idx < NTOK * 4; idx += 128) {
        int i = idx >> 2, ch = (idx & 3) * 8;
        const __half* rp = qbase + (size_t)i * QKVDIM;
        *reinterpret_cast<uint4*>(&qs[i][ch])     = *reinterpret_cast<const uint4*>(rp + ch);
        *reinterpret_cast<uint4*>(&ks[i + NMEM][ch]) = *reinterpret_cast<const uint4*>(rp + DIM + ch);
        *reinterpret_cast<uint4*>(&vs[i + NMEM][ch]) = *reinterpret_cast<const uint4*>(rp + 2 * DIM + ch);
    }
    for (int idx = tid; idx < 2 * NMEM * DH; idx += 128) {
        int which = idx >> 7;            // 0 = k, 1 = v
        int r = (idx >> 5) & 3;
        int d = idx & 31;
        float val = mem_kv[which * (NHEAD * NMEM * DH) + (h * NMEM + r) * DH + d];
        (which ? vs : ks)[r][d] = __float2half_rn(val);
    }
    __syncthreads();

    const uint32_t smq = smem_u32(qs);
    const uint32_t smk = smem_u32(ks);
    const uint32_t smv = smem_u32(vs);

    // ---- QK: warp m-tile = wid, 8 n-tiles, k=32 (2 k16 steps)
    float s[8][4];
#pragma unroll
    for (int t = 0; t < 8; t++)
#pragma unroll
        for (int l = 0; l < 4; l++) s[t][l] = 0.f;

    const int arow = lane & 15;
    const int akof = (lane >> 4) << 3;
    const int brow = (lane & 7) + ((lane >> 4) << 3);
    const int bkof = ((lane >> 3) & 1) << 3;

#pragma unroll
    for (int k2 = 0; k2 < 2; k2++) {
        uint32_t a[4];
        ldmx4(a, smq + (uint32_t)(wid * 16 + arow) * 80u + (uint32_t)(k2 * 16 + akof) * 2u);
#pragma unroll
        for (int p = 0; p < 4; p++) {
            uint32_t r4[4];
            ldmx4(r4, smk + (uint32_t)(p * 16 + brow) * 80u + (uint32_t)(k2 * 16 + bkof) * 2u);
            mma_f16(s[2 * p], a, r4);
            mma_f16(s[2 * p + 1], a, r4 + 2);
        }
    }

    // ---- scale + bias + mask
    const float scale = 0.17677669529663687f;   // 1/sqrt(32)
    const int row0 = wid * 16 + (lane >> 2);
    const int row1 = row0 + 8;
    const int c0 = (lane & 3) * 2;
    const float* gb0 = g_bias + (h * 49 + min(row0, 48)) * 64;
    const float* gb1 = g_bias + (h * 49 + min(row1, 48)) * 64;
#pragma unroll
    for (int t = 0; t < 8; t++) {
        int j0 = t * 8 + c0, j1 = j0 + 1;
        s[t][0] = (j0 < NCTX) ? s[t][0] * scale + gb0[j0] : -1e30f;
        s[t][1] = (j1 < NCTX) ? s[t][1] * scale + gb0[j1] : -1e30f;
        s[t][2] = (j0 < NCTX) ? s[t][2] * scale + gb1[j0] : -1e30f;
        s[t][3] = (j1 < NCTX) ? s[t][3] * scale + gb1[j1] : -1e30f;
    }

    // ---- softmax (rows split across 4-lane groups)
    float m0 = -1e30f, m1 = -1e30f;
#pragma unroll
    for (int t = 0; t < 8; t++) {
        m0 = fmaxf(m0, fmaxf(s[t][0], s[t][1]));
        m1 = fmaxf(m1, fmaxf(s[t][2], s[t][3]));
    }
    m0 = fmaxf(m0, __shfl_xor_sync(0xffffffffu, m0, 1));
    m0 = fmaxf(m0, __shfl_xor_sync(0xffffffffu, m0, 2));
    m1 = fmaxf(m1, __shfl_xor_sync(0xffffffffu, m1, 1));
    m1 = fmaxf(m1, __shfl_xor_sync(0xffffffffu, m1, 2));
    float sum0 = 0.f, sum1 = 0.f;
#pragma unroll
    for (int t = 0; t < 8; t++) {
        s[t][0] = __expf(s[t][0] - m0);
        s[t][1] = __expf(s[t][1] - m0);
        s[t][2] = __expf(s[t][2] - m1);
        s[t][3] = __expf(s[t][3] - m1);
        sum0 += s[t][0] + s[t][1];
        sum1 += s[t][2] + s[t][3];
    }
    sum0 += __shfl_xor_sync(0xffffffffu, sum0, 1);
    sum0 += __shfl_xor_sync(0xffffffffu, sum0, 2);
    sum1 += __shfl_xor_sync(0xffffffffu, sum1, 1);
    sum1 += __shfl_xor_sync(0xffffffffu, sum1, 2);
    float inv0 = 1.f / sum0, inv1 = 1.f / sum1;
#pragma unroll
    for (int t = 0; t < 8; t++) {
        s[t][0] *= inv0; s[t][1] *= inv0;
        s[t][2] *= inv1; s[t][3] *= inv1;
    }

    // ---- PV: P (fp16 A-frags from regs) @ V (B-frags via ldmatrix.trans)
    float o[4][4];
#pragma unroll
    for (int dt = 0; dt < 4; dt++)
#pragma unroll
        for (int l = 0; l < 4; l++) o[dt][l] = 0.f;

#pragma unroll
    for (int kb = 0; kb < 4; kb++) {
        uint32_t pa[4];
        pa[0] = packh2(s[2 * kb][0], s[2 * kb][1]);
        pa[1] = packh2(s[2 * kb][2], s[2 * kb][3]);
        pa[2] = packh2(s[2 * kb + 1][0], s[2 * kb + 1][1]);
        pa[3] = packh2(s[2 * kb + 1][2], s[2 * kb + 1][3]);
#pragma unroll
        for (int q = 0; q < 2; q++) {
            uint32_t r4[4];
            ldmx4t(r4, smv + (uint32_t)(kb * 16 + (lane & 15)) * 80u
                       + (uint32_t)(((lane >> 4) << 3) + q * 16) * 2u);
            mma_f16(o[2 * q], pa, r4);
            mma_f16(o[2 * q + 1], pa, r4 + 2);
        }
    }

    // ---- store rows < 49 to g_ah (merged heads, fp16)
    if (row0 < NTOK) {
        __half* op = g_ah + ((size_t)w * NTOK + row0) * DIM + h * DH;
#pragma unroll
        for (int dt = 0; dt < 4; dt++)
            *reinterpret_cast<__half2*>(op + dt * 8 + c0)
                = __floats2half2_rn(o[dt][0], o[dt][1]);
    }
    if (row1 < NTOK) {
        __half* op = g_ah + ((size_t)w * NTOK + row1) * DIM + h * DH;
#pragma unroll
        for (int dt = 0; dt < 4; dt++)
            *reinterpret_cast<__half2*>(op + dt * 8 + c0)
                = __floats2half2_rn(o[dt][2], o[dt][3]);
    }
}

// ---------------------------------------------------------------------------
// Launch
// ---------------------------------------------------------------------------
extern "C" void kernel_launch(void* const* d_in, const int* in_sizes, int n_in,
                              void* d_out, int out_size) {
    const float* x        = (const float*)d_in[0];
    const float* ln_gamma = (const float*)d_in[1];
    const float* ln_beta  = (const float*)d_in[2];
    const float* w_qkv    = (const float*)d_in[3];
    const float* mem_kv   = (const float*)d_in[4];
    const float* w_out    = (const float*)d_in[5];
    const float* rel_bias = (const float*)d_in[6];
    const int*   rel_idx  = (const int*)d_in[7];
    float* out = (float*)d_out;

    static bool attr_set = false;
    if (!attr_set) {
        cudaFuncSetAttribute(gemm_mma_kernel<0>, cudaFuncAttributeMaxDynamicSharedMemorySize, GSMEM);
        cudaFuncSetAttribute(gemm_mma_kernel<1>, cudaFuncAttributeMaxDynamicSharedMemorySize, GSMEM);
        attr_set = true;
    }

    __half *wqh, *woh;
    cudaGetSymbolAddress((void**)&wqh, g_wqkv_h);
    cudaGetSymbolAddress((void**)&woh, g_wout_h);

    // 1) fused LN -> fp16
    ln_prep_kernel<<<NROWS / 8, 256>>>(x, ln_gamma, ln_beta);

    // 2) weight transpose -> fp16 + per-head bias table (tiny)
    transpose_h_kernel<<<dim3(QKVDIM / 32, DIM / 32), 256>>>(w_qkv, wqh, DIM, QKVDIM);
    transpose_h_kernel<<<dim3(DIM / 32, DIM / 32), 256>>>(w_out, woh, DIM, DIM);
    bias_prep_kernel<<<(16 * 49 * 64 + 255) / 256, 256>>>(rel_bias, rel_idx);

    // 3) QKV GEMM (tensor cores): g_qkv = LN(x) @ w_qkv  (fp16 out)
    gemm_mma_kernel<0><<<dim3(QKVDIM / 128, NROWS / 128), 256, GSMEM>>>(nullptr);

    // 4) tensor-core windowed attention per (window, head) -> g_ah (fp16)
    attn_kernel<<<dim3(NWIN, NHEAD), 128>>>(mem_kv);

    // 5) output projection (tensor cores): out = attn_out @ w_out
    gemm_mma_kernel<1><<<dim3(DIM / 128, NROWS / 128), 256, GSMEM>>>(out);
}

// round 8
// speedup vs baseline: 6.4100x; 1.1376x over previous
#include <cuda_runtime.h>
#include <cuda_fp16.h>
#include <cstdint>

// Problem constants
#define NROWS   100352        // 2048 windows * 49 tokens
#define DIM     512
#define QKVDIM  1536
#define NWIN    2048
#define NTOK    49
#define NHEAD   16
#define DH      32
#define NMEM    4
#define NCTX    53            // NMEM + NTOK
#define GK      512           // GEMM K (both GEMMs)

// ---------------------------------------------------------------------------
// Scratch (device globals: no allocation allowed anywhere)
// ---------------------------------------------------------------------------
__device__ __half g_qkv[(size_t)NROWS * QKVDIM];      // 308 MB fp16
__device__ __half g_xh[(size_t)NROWS * DIM];          // LN(x) fp16
__device__ __half g_ah[(size_t)NROWS * DIM];          // attn out fp16
__device__ __half g_wqkv_h[(size_t)QKVDIM * DIM];     // w_qkv^T fp16 [N][K]
__device__ __half g_wout_h[(size_t)DIM * DIM];        // w_out^T fp16 [N][K]
__device__ __half g_biash[16 * 49 * 64];              // per-head bias fp16, mask folded

// ---------------------------------------------------------------------------
// PTX helpers (baseline PTX only -- harness builds for compute_103)
// ---------------------------------------------------------------------------
__device__ __forceinline__ uint32_t smem_u32(const void* p) {
    uint32_t a;
    asm("{ .reg .u64 t; cvta.to.shared.u64 t, %1; cvt.u32.u64 %0, t; }" : "=r"(a) : "l"(p));
    return a;
}
__device__ __forceinline__ void ldmx4(uint32_t* r, uint32_t addr) {
    asm volatile("ldmatrix.sync.aligned.m8n8.x4.shared.b16 {%0,%1,%2,%3}, [%4];"
        : "=r"(r[0]), "=r"(r[1]), "=r"(r[2]), "=r"(r[3]) : "r"(addr));
}
__device__ __forceinline__ void ldmx4t(uint32_t* r, uint32_t addr) {
    asm volatile("ldmatrix.sync.aligned.m8n8.x4.trans.shared.b16 {%0,%1,%2,%3}, [%4];"
        : "=r"(r[0]), "=r"(r[1]), "=r"(r[2]), "=r"(r[3]) : "r"(addr));
}
__device__ __forceinline__ void mma_f16(float* c, const uint32_t* a, const uint32_t* b) {
    asm volatile(
        "mma.sync.aligned.m16n8k16.row.col.f32.f16.f16.f32 "
        "{%0,%1,%2,%3}, {%4,%5,%6,%7}, {%8,%9}, {%0,%1,%2,%3};"
        : "+f"(c[0]), "+f"(c[1]), "+f"(c[2]), "+f"(c[3])
        : "r"(a[0]), "r"(a[1]), "r"(a[2]), "r"(a[3]), "r"(b[0]), "r"(b[1]));
}
__device__ __forceinline__ uint32_t packh2(float a, float b) {
    __half2 t = __floats2half2_rn(a, b);
    return *reinterpret_cast<uint32_t*>(&t);
}
#define CP_ASYNC16(dst, src) \
    asm volatile("cp.async.cg.shared.global [%0], [%1], 16;" :: "r"(dst), "l"(src) : "memory")
#define CP_COMMIT() asm volatile("cp.async.commit_group;" ::: "memory")
#define CP_WAIT1()  asm volatile("cp.async.wait_group 1;" ::: "memory")
#define CP_WAIT0()  asm volatile("cp.async.wait_group 0;" ::: "memory")

// ---------------------------------------------------------------------------
// Kernel 1: fused LayerNorm -> fp16.  One warp per row of 512.
// ---------------------------------------------------------------------------
__global__ void __launch_bounds__(256) ln_prep_kernel(
    const float* __restrict__ x,
    const float* __restrict__ gamma, const float* __restrict__ beta)
{
    int row  = blockIdx.x * 8 + (threadIdx.x >> 5);
    int lane = threadIdx.x & 31;
    const float4* xp = reinterpret_cast<const float4*>(x + (size_t)row * DIM);
    float4 v[4];
    float s = 0.f, sq = 0.f;
#pragma unroll
    for (int i = 0; i < 4; i++) {
        v[i] = xp[lane + i * 32];
        s  += v[i].x + v[i].y + v[i].z + v[i].w;
        sq += v[i].x * v[i].x + v[i].y * v[i].y + v[i].z * v[i].z + v[i].w * v[i].w;
    }
#pragma unroll
    for (int o = 16; o; o >>= 1) {
        s  += __shfl_xor_sync(0xffffffffu, s,  o);
        sq += __shfl_xor_sync(0xffffffffu, sq, o);
    }
    float m   = s * (1.f / DIM);
    float var = sq * (1.f / DIM) - m * m;
    float rs  = rsqrtf(var + 1e-5f);
#pragma unroll
    for (int i = 0; i < 4; i++) {
        int col = (lane + i * 32) * 4;
        float4 gm = *reinterpret_cast<const float4*>(gamma + col);
        float4 bt = *reinterpret_cast<const float4*>(beta + col);
        float y0 = (v[i].x - m) * rs * gm.x + bt.x;
        float y1 = (v[i].y - m) * rs * gm.y + bt.y;
        float y2 = (v[i].z - m) * rs * gm.z + bt.z;
        float y3 = (v[i].w - m) * rs * gm.w + bt.w;
        size_t off = (size_t)row * DIM + col;
        __half2* hp = reinterpret_cast<__half2*>(&g_xh[off]);
        hp[0] = __floats2half2_rn(y0, y1);
        hp[1] = __floats2half2_rn(y2, y3);
    }
}

// ---------------------------------------------------------------------------
// Kernel 2: transpose weights [K,N] -> [N,K] fp16
// ---------------------------------------------------------------------------
__global__ void __launch_bounds__(256) transpose_h_kernel(
    const float* __restrict__ src, __half* __restrict__ dst, int K, int N)
{
    __shared__ float t[32][33];
    int bx = blockIdx.x * 32;   // n base
    int by = blockIdx.y * 32;   // k base
    int tx = threadIdx.x & 31, ty = threadIdx.x >> 5;
#pragma unroll
    for (int u = 0; u < 4; u++)
        t[ty + u * 8][tx] = src[(size_t)(by + ty + u * 8) * N + bx + tx];
    __syncthreads();
#pragma unroll
    for (int u = 0; u < 4; u++)
        dst[(size_t)(bx + ty + u * 8) * K + by + tx] = __float2half_rn(t[tx][ty + u * 8]);
}

// ---------------------------------------------------------------------------
// Kernel 3: per-head bias table, fp16, ctx mask folded in (-6e4 for j>=NCTX)
// ---------------------------------------------------------------------------
__global__ void __launch_bounds__(256) bias_prep_kernel(
    const float* __restrict__ rel_bias, const int* __restrict__ rel_idx)
{
    int idx = blockIdx.x * 256 + threadIdx.x;
    if (idx >= 16 * 49 * 64) return;
    int h = idx / (49 * 64);
    int rem = idx - h * 49 * 64;
    int i = rem >> 6;
    int j = rem & 63;
    float v;
    if (j >= NCTX)      v = -60000.f;
    else if (j < NMEM)  v = 0.f;
    else                v = rel_bias[rel_idx[i * NTOK + (j - NMEM)] * NHEAD + h];
    g_biash[idx] = __float2half_rn(v);
}

// ---------------------------------------------------------------------------
// Tensor-core GEMM, fp16 operands, 3-stage cp.async pipeline, K-slab 64.
// CTA tile 128x128, 8 warps (warp tile 64x32), 2 CTAs/SM.
// MODE 0: A = g_xh, B = w_qkv^T, C = g_qkv (fp16, N=1536)
// MODE 1: A = g_ah, B = w_out^T, C = out (fp32, N=512)
// ---------------------------------------------------------------------------
#define ROWB     144u                // 64 halves * 2B + 16B pad
#define TILE_B   18432u              // 128 rows * 144 B
#define STAGE_B  36864u              // 2 tiles (A,B)
#define GSMEM    110592              // 3 stages

template <int MODE>
__global__ void __launch_bounds__(256, 2) gemm_mma_kernel(float* __restrict__ Cout)
{
    extern __shared__ char smem[];
    const uint32_t sbase = smem_u32(smem);

    const int N = (MODE == 0) ? QKVDIM : DIM;
    const __half* __restrict__ Ah = (MODE == 0) ? g_xh : g_ah;
    const __half* __restrict__ Bh = (MODE == 0) ? g_wqkv_h : g_wout_h;

    const int tid  = threadIdx.x;
    const int lane = tid & 31;
    const int wid  = tid >> 5;
    const int bm   = blockIdx.y * 128;
    const int bn   = blockIdx.x * 128;
    const int wm   = (wid & 1) * 64;
    const int wn   = (wid >> 1) * 32;

    float c[4][4][4];
#pragma unroll
    for (int i = 0; i < 4; i++)
#pragma unroll
        for (int j = 0; j < 4; j++)
#pragma unroll
            for (int l = 0; l < 4; l++) c[i][j][l] = 0.f;

    // stage copy: A tile 128x64 fp16 + B tile 128x64 fp16 = 2048 16B-chunks
    auto issue_stage = [&](int buf, int k0) {
#pragma unroll
        for (int u = 0; u < 8; u++) {
            int id   = tid + u * 256;
            int tile = id >> 10;              // 0 = A, 1 = B
            int id10 = id & 1023;
            int r    = id10 >> 3;
            int cch  = id10 & 7;              // 16B chunk (8 halves)
            int grow = ((tile == 0) ? bm : bn) + r;
            const void* src = ((tile == 0) ? Ah : Bh) + (size_t)grow * GK + k0 + cch * 8;
            uint32_t dst = sbase + (uint32_t)buf * STAGE_B + (uint32_t)tile * TILE_B
                         + (uint32_t)r * ROWB + (uint32_t)cch * 16u;
            CP_ASYNC16(dst, src);
        }
        CP_COMMIT();
    };

    issue_stage(0, 0);
    issue_stage(1, 64);

    const int arow = lane & 15;
    const int akof = (lane >> 4) << 3;
    const int brow = (lane & 7) + ((lane >> 4) << 3);
    const int bkof = ((lane >> 3) & 1) << 3;

    for (int it = 0; it < 8; ++it) {
        if (it < 7) CP_WAIT1(); else CP_WAIT0();
        __syncthreads();
        if (it + 2 < 8) issue_stage((it + 2) % 3, (it + 2) * 64);

        const uint32_t st  = sbase + (uint32_t)(it % 3) * STAGE_B;
        const uint32_t pAh = st;
        const uint32_t pBh = st + TILE_B;

#pragma unroll
        for (int h = 0; h < 4; h++) {         // four k16 steps of the 64-slab
            const uint32_t acol = (uint32_t)(h * 16 + akof) * 2u;
            const uint32_t bcol = (uint32_t)(h * 16 + bkof) * 2u;
            uint32_t ah[4][4], bh[4][2];
#pragma unroll
            for (int mt = 0; mt < 4; mt++)
                ldmx4(ah[mt], pAh + (uint32_t)(wm + mt * 16 + arow) * ROWB + acol);
#pragma unroll
            for (int p = 0; p < 2; p++) {
                uint32_t r4[4];
                ldmx4(r4, pBh + (uint32_t)(wn + p * 16 + brow) * ROWB + bcol);
                bh[2 * p][0] = r4[0]; bh[2 * p][1] = r4[1];
                bh[2 * p + 1][0] = r4[2]; bh[2 * p + 1][1] = r4[3];
            }
#pragma unroll
            for (int mt = 0; mt < 4; mt++)
#pragma unroll
                for (int nt = 0; nt < 4; nt++) mma_f16(c[mt][nt], ah[mt], bh[nt]);
        }
    }

    // epilogue
#pragma unroll
    for (int mt = 0; mt < 4; mt++) {
        int row0 = bm + wm + mt * 16 + (lane >> 2);
#pragma unroll
        for (int nt = 0; nt < 4; nt++) {
            int col = bn + wn + nt * 8 + (lane & 3) * 2;
            if (MODE == 0) {
                *reinterpret_cast<__half2*>(&g_qkv[(size_t)row0 * N + col])
                    = __floats2half2_rn(c[mt][nt][0], c[mt][nt][1]);
                *reinterpret_cast<__half2*>(&g_qkv[(size_t)(row0 + 8) * N + col])
                    = __floats2half2_rn(c[mt][nt][2], c[mt][nt][3]);
            } else {
                *reinterpret_cast<float2*>(Cout + (size_t)row0 * N + col)
                    = make_float2(c[mt][nt][0], c[mt][nt][1]);
                *reinterpret_cast<float2*>(Cout + (size_t)(row0 + 8) * N + col)
                    = make_float2(c[mt][nt][2], c[mt][nt][3]);
            }
        }
    }
}

// ---------------------------------------------------------------------------
// Kernel: tensor-core windowed attention, one block (4 warps) per (window, head).
// M padded to 64 (4 warp m-tiles of 16), ctx padded to 64 (8 n-tiles).
// QK mma -> fp32 softmax in regs -> P as fp16 A-frags -> PV mma (V via ldmatrix.trans).
// ---------------------------------------------------------------------------
__global__ void __launch_bounds__(128) attn_kernel(const float* __restrict__ mem_kv)
{
    const int w = blockIdx.x;
    const int h = blockIdx.y;
    const int tid = threadIdx.x;
    const int lane = tid & 31;
    const int wid = tid >> 5;

    __shared__ alignas(16) __half qs[64][40];
    __shared__ alignas(16) __half ks[64][40];
    __shared__ alignas(16) __half vs[64][40];

    // zero-pad all tiles (rows beyond valid range must be 0)
    {
        uint4 z = make_uint4(0, 0, 0, 0);
        uint4* q4 = reinterpret_cast<uint4*>(&qs[0][0]);
        uint4* k4 = reinterpret_cast<uint4*>(&ks[0][0]);
        uint4* v4 = reinterpret_cast<uint4*>(&vs[0][0]);
        for (int i = tid; i < 320; i += 128) { q4[i] = z; k4[i] = z; v4[i] = z; }
    }
    __syncthreads();

    // fill q (rows 0..48), k/v (rows 4..52 from qkv, rows 0..3 from mem_kv)
    const __half* qbase = g_qkv + (size_t)w * NTOK * QKVDIM + h * DH;
    for (int idx = tid; idx < NTOK * 4; idx += 128) {
        int i = idx >> 2, ch = (idx & 3) * 8;
        const __half* rp = qbase + (size_t)i * QKVDIM;
        *reinterpret_cast<uint4*>(&qs[i][ch])     = *reinterpret_cast<const uint4*>(rp + ch);
        *reinterpret_cast<uint4*>(&ks[i + NMEM][ch]) = *reinterpret_cast<const uint4*>(rp + DIM + ch);
        *reinterpret_cast<uint4*>(&vs[i + NMEM][ch]) = *reinterpret_cast<const uint4*>(rp + 2 * DIM + ch);
    }
    for (int idx = tid; idx < 2 * NMEM * DH; idx += 128) {
        int which = idx >> 7;            // 0 = k, 1 = v
        int r = (idx >> 5) & 3;
        int d = idx & 31;
        float val = mem_kv[which * (NHEAD * NMEM * DH) + (h * NMEM + r) * DH + d];
        (which ? vs : ks)[r][d] = __float2half_rn(val);
    }
    __syncthreads();

    const uint32_t smq = smem_u32(qs);
    const uint32_t smk = smem_u32(ks);
    const uint32_t smv = smem_u32(vs);

    // ---- QK: warp m-tile = wid, 8 n-tiles, k=32 (2 k16 steps)
    float s[8][4];
#pragma unroll
    for (int t = 0; t < 8; t++)
#pragma unroll
        for (int l = 0; l < 4; l++) s[t][l] = 0.f;

    const int arow = lane & 15;
    const int akof = (lane >> 4) << 3;
    const int brow = (lane & 7) + ((lane >> 4) << 3);
    const int bkof = ((lane >> 3) & 1) << 3;

#pragma unroll
    for (int k2 = 0; k2 < 2; k2++) {
        uint32_t a[4];
        ldmx4(a, smq + (uint32_t)(wid * 16 + arow) * 80u + (uint32_t)(k2 * 16 + akof) * 2u);
#pragma unroll
        for (int p = 0; p < 4; p++) {
            uint32_t r4[4];
            ldmx4(r4, smk + (uint32_t)(p * 16 + brow) * 80u + (uint32_t)(k2 * 16 + bkof) * 2u);
            mma_f16(s[2 * p], a, r4);
            mma_f16(s[2 * p + 1], a, r4 + 2);
        }
    }

    // ---- scale + bias (mask folded into bias table)
    const float scale = 0.17677669529663687f;   // 1/sqrt(32)
    const int row0 = wid * 16 + (lane >> 2);
    const int row1 = row0 + 8;
    const int c0 = (lane & 3) * 2;
    const __half* gb0 = g_biash + (h * 49 + min(row0, 48)) * 64;
    const __half* gb1 = g_biash + (h * 49 + min(row1, 48)) * 64;
#pragma unroll
    for (int t = 0; t < 8; t++) {
        float2 b0 = __half22float2(*reinterpret_cast<const __half2*>(gb0 + t * 8 + c0));
        float2 b1 = __half22float2(*reinterpret_cast<const __half2*>(gb1 + t * 8 + c0));
        s[t][0] = s[t][0] * scale + b0.x;
        s[t][1] = s[t][1] * scale + b0.y;
        s[t][2] = s[t][2] * scale + b1.x;
        s[t][3] = s[t][3] * scale + b1.y;
    }

    // ---- softmax (rows split across 4-lane groups)
    float m0 = -1e30f, m1 = -1e30f;
#pragma unroll
    for (int t = 0; t < 8; t++) {
        m0 = fmaxf(m0, fmaxf(s[t][0], s[t][1]));
        m1 = fmaxf(m1, fmaxf(s[t][2], s[t][3]));
    }
    m0 = fmaxf(m0, __shfl_xor_sync(0xffffffffu, m0, 1));
    m0 = fmaxf(m0, __shfl_xor_sync(0xffffffffu, m0, 2));
    m1 = fmaxf(m1, __shfl_xor_sync(0xffffffffu, m1, 1));
    m1 = fmaxf(m1, __shfl_xor_sync(0xffffffffu, m1, 2));
    float sum0 = 0.f, sum1 = 0.f;
#pragma unroll
    for (int t = 0; t < 8; t++) {
        s[t][0] = __expf(s[t][0] - m0);
        s[t][1] = __expf(s[t][1] - m0);
        s[t][2] = __expf(s[t][2] - m1);
        s[t][3] = __expf(s[t][3] - m1);
        sum0 += s[t][0] + s[t][1];
        sum1 += s[t][2] + s[t][3];
    }
    sum0 += __shfl_xor_sync(0xffffffffu, sum0, 1);
    sum0 += __shfl_xor_sync(0xffffffffu, sum0, 2);
    sum1 += __shfl_xor_sync(0xffffffffu, sum1, 1);
    sum1 += __shfl_xor_sync(0xffffffffu, sum1, 2);
    float inv0 = 1.f / sum0, inv1 = 1.f / sum1;
#pragma unroll
    for (int t = 0; t < 8; t++) {
        s[t][0] *= inv0; s[t][1] *= inv0;
        s[t][2] *= inv1; s[t][3] *= inv1;
    }

    // ---- PV: P (fp16 A-frags from regs) @ V (B-frags via ldmatrix.trans)
    float o[4][4];
#pragma unroll
    for (int dt = 0; dt < 4; dt++)
#pragma unroll
        for (int l = 0; l < 4; l++) o[dt][l] = 0.f;

#pragma unroll
    for (int kb = 0; kb < 4; kb++) {
        uint32_t pa[4];
        pa[0] = packh2(s[2 * kb][0], s[2 * kb][1]);
        pa[1] = packh2(s[2 * kb][2], s[2 * kb][3]);
        pa[2] = packh2(s[2 * kb + 1][0], s[2 * kb + 1][1]);
        pa[3] = packh2(s[2 * kb + 1][2], s[2 * kb + 1][3]);
#pragma unroll
        for (int q = 0; q < 2; q++) {
            uint32_t r4[4];
            ldmx4t(r4, smv + (uint32_t)(kb * 16 + (lane & 15)) * 80u
                       + (uint32_t)(((lane >> 4) << 3) + q * 16) * 2u);
            mma_f16(o[2 * q], pa, r4);
            mma_f16(o[2 * q + 1], pa, r4 + 2);
        }
    }

    // ---- store rows < 49 to g_ah (merged heads, fp16)
    if (row0 < NTOK) {
        __half* op = g_ah + ((size_t)w * NTOK + row0) * DIM + h * DH;
#pragma unroll
        for (int dt = 0; dt < 4; dt++)
            *reinterpret_cast<__half2*>(op + dt * 8 + c0)
                = __floats2half2_rn(o[dt][0], o[dt][1]);
    }
    if (row1 < NTOK) {
        __half* op = g_ah + ((size_t)w * NTOK + row1) * DIM + h * DH;
#pragma unroll
        for (int dt = 0; dt < 4; dt++)
            *reinterpret_cast<__half2*>(op + dt * 8 + c0)
                = __floats2half2_rn(o[dt][2], o[dt][3]);
    }
}

// ---------------------------------------------------------------------------
// Launch
// ---------------------------------------------------------------------------
extern "C" void kernel_launch(void* const* d_in, const int* in_sizes, int n_in,
                              void* d_out, int out_size) {
    const float* x        = (const float*)d_in[0];
    const float* ln_gamma = (const float*)d_in[1];
    const float* ln_beta  = (const float*)d_in[2];
    const float* w_qkv    = (const float*)d_in[3];
    const float* mem_kv   = (const float*)d_in[4];
    const float* w_out    = (const float*)d_in[5];
    const float* rel_bias = (const float*)d_in[6];
    const int*   rel_idx  = (const int*)d_in[7];
    float* out = (float*)d_out;

    static bool attr_set = false;
    if (!attr_set) {
        cudaFuncSetAttribute(gemm_mma_kernel<0>, cudaFuncAttributeMaxDynamicSharedMemorySize, GSMEM);
        cudaFuncSetAttribute(gemm_mma_kernel<1>, cudaFuncAttributeMaxDynamicSharedMemorySize, GSMEM);
        attr_set = true;
    }

    __half *wqh, *woh;
    cudaGetSymbolAddress((void**)&wqh, g_wqkv_h);
    cudaGetSymbolAddress((void**)&woh, g_wout_h);

    // 1) fused LN -> fp16
    ln_prep_kernel<<<NROWS / 8, 256>>>(x, ln_gamma, ln_beta);

    // 2) weight transpose -> fp16 + per-head bias table (tiny)
    transpose_h_kernel<<<dim3(QKVDIM / 32, DIM / 32), 256>>>(w_qkv, wqh, DIM, QKVDIM);
    transpose_h_kernel<<<dim3(DIM / 32, DIM / 32), 256>>>(w_out, woh, DIM, DIM);
    bias_prep_kernel<<<(16 * 49 * 64 + 255) / 256, 256>>>(rel_bias, rel_idx);

    // 3) QKV GEMM (tensor cores): g_qkv = LN(x) @ w_qkv  (fp16 out)
    gemm_mma_kernel<0><<<dim3(QKVDIM / 128, NROWS / 128), 256, GSMEM>>>(nullptr);

    // 4) tensor-core windowed attention per (window, head) -> g_ah (fp16)
    attn_kernel<<<dim3(NWIN, NHEAD), 128>>>(mem_kv);

    // 5) output projection (tensor cores): out = attn_out @ w_out
    gemm_mma_kernel<1><<<dim3(DIM / 128, NROWS / 128), 256, GSMEM>>>(out);
}